// round 2
// baseline (speedup 1.0000x reference)
#include <cuda_runtime.h>
#include <cuda_bf16.h>
#include <cstdint>

#define BTOK 262144
#define DM 128
#define DFF 512
#define NT 16
#define NOPS 8
#define EMB 32
#define MROWS 128
#define NCHUNK 4
#define SLD 132
#define MAXBLK (BTOK/MROWS + NT)
#define PADB (BTOK + NT*MROWS)

// ---------------- device scratch (no allocation allowed) ----------------
__device__ float g_Tf[NOPS*DM];
__device__ float g_Tg[256*DM];
__device__ float g_Th[256*DM];
__device__ float g_Lf[NOPS*NT];
__device__ float g_Lg[256*NT];
__device__ float g_Lh[256*NT];
__device__ float g_Lc[NT];
__device__ float g_Lb[NT];
__device__ float g_s1[NT], g_s2[NT];
__device__ double g_res[2];
__device__ signed char g_W1q[NT*DFF*DM];   // [t][n(dff)][k(d)]
__device__ signed char g_W2q[NT*DM*DFF];   // [t][n(d)][k(dff)]
__device__ int g_cnt[NT];
__device__ double g_sumP[NT];
__device__ int g_fill[NT];
__device__ int g_po[NT];
__device__ int g_nblocks;
__device__ unsigned char g_idx[BTOK];
__device__ float g_gate[BTOK];
__device__ int g_src[PADB];
__device__ int g_bmT[MAXBLK];
__device__ int g_bmR[MAXBLK];

// ---------------- helpers ----------------
__device__ __forceinline__ uint32_t f2tf(float v){
    uint32_t r; asm("cvt.rna.tf32.f32 %0, %1;" : "=r"(r) : "f"(v)); return r;
}
__device__ __forceinline__ void mma8(float* c, const uint32_t* a, const uint32_t* b){
    asm volatile("mma.sync.aligned.m16n8k8.row.col.f32.tf32.tf32.f32 "
        "{%0,%1,%2,%3},{%4,%5,%6,%7},{%8,%9},{%0,%1,%2,%3};"
        : "+f"(c[0]),"+f"(c[1]),"+f"(c[2]),"+f"(c[3])
        : "r"(a[0]),"r"(a[1]),"r"(a[2]),"r"(a[3]),"r"(b[0]),"r"(b[1]));
}

// ---------------- k_init ----------------
__global__ void k_init(){
    int i = threadIdx.x;
    if (i < NT){ g_cnt[i]=0; g_sumP[i]=0.0; g_fill[i]=0; }
    if (i < 2)  g_res[i]=0.0;
}

// ---------------- k_tables: feature tables ----------------
__global__ void k_tables(const float* __restrict__ oe, const float* __restrict__ Win){
    int gid = blockIdx.x*256 + threadIdx.x;
    if (gid < 32768){
        int av = gid >> 7, d = gid & 127;
        float s = 0.f;
        #pragma unroll
        for (int i=0;i<8;i++) if ((av>>i)&1) s += Win[(32+i)*DM + d];
        g_Tg[av*DM+d] = s;
    } else if (gid < 65536){
        int g2 = gid - 32768;
        int bv = g2 >> 7, d = g2 & 127;
        float s = 0.f;
        #pragma unroll
        for (int i=0;i<8;i++) if ((bv>>i)&1) s += Win[(40+i)*DM + d];
        g_Th[bv*DM+d] = s;
    } else if (gid < 66560){
        int g2 = gid - 65536;
        int op = g2 >> 7, d = g2 & 127;
        float s = 0.f;
        #pragma unroll
        for (int j=0;j<EMB;j++) s += oe[op*EMB+j]*Win[j*DM+d];
        g_Tf[op*DM+d] = s;
    }
}

// ---------------- k_lt: router logit tables ----------------
__global__ void k_lt(const float* __restrict__ Wr, const float* __restrict__ Win,
                     const float* __restrict__ bin){
    int gid = blockIdx.x*256+threadIdx.x;
    if (gid < 4096){
        int av=gid>>4, t=gid&15; float s=0.f;
        for(int d=0;d<DM;d++) s += g_Tg[av*DM+d]*Wr[d*NT+t];
        g_Lg[gid]=s;
    } else if (gid < 8192){
        int g2=gid-4096; int bv=g2>>4,t=g2&15; float s=0.f;
        for(int d=0;d<DM;d++) s += g_Th[bv*DM+d]*Wr[d*NT+t];
        g_Lh[g2]=s;
    } else if (gid < 8320){
        int g2=gid-8192; int op=g2>>4,t=g2&15; float s=0.f;
        for(int d=0;d<DM;d++) s += g_Tf[op*DM+d]*Wr[d*NT+t];
        g_Lf[g2]=s;
    } else if (gid < 8336){
        int t=gid-8320; float s=0.f;
        for(int d=0;d<DM;d++) s += Win[48*DM+d]*Wr[d*NT+t];
        g_Lc[t]=s;
    } else if (gid < 8352){
        int t=gid-8336; float s=0.f;
        for(int d=0;d<DM;d++) s += bin[d]*Wr[d*NT+t];
        g_Lb[t]=s;
    }
}

// ---------------- k_scale: per-tile mean |W| ----------------
__global__ void k_scale(const float* __restrict__ W1, const float* __restrict__ W2){
    __shared__ double red[256];
    int m = blockIdx.x >> 4, t = blockIdx.x & 15;
    const float* W = (m? W2 : W1) + t*65536;
    double s=0.0;
    for (int i=threadIdx.x; i<65536; i+=256) s += (double)fabsf(W[i]);
    red[threadIdx.x]=s; __syncthreads();
    for (int o=128;o;o>>=1){ if(threadIdx.x<o) red[threadIdx.x]+=red[threadIdx.x+o]; __syncthreads(); }
    if (!threadIdx.x){
        float v = (float)(red[0]/65536.0);
        if(m) g_s2[t]=v; else g_s1[t]=v;
    }
}

// ---------------- k_quant: ternary signs (transposed) + residual ----------------
__global__ void k_quant(const float* __restrict__ W1, const float* __restrict__ W2){
    __shared__ double red[256];
    int gid = blockIdx.x*256+threadIdx.x;
    int m = gid >> 20;
    int e = gid & 0xFFFFF;
    int t = e >> 16, j = e & 0xFFFF;
    float w, s; int outi;
    if (!m){ w = W1[e]; s = g_s1[t]; int k=j>>9, n=j&511; outi = t*65536 + n*128 + k; }
    else   { w = W2[e]; s = g_s2[t]; int kk=j>>7, nn=j&127; outi = t*65536 + nn*512 + kk; }
    float aw = fabsf(w);
    bool nz = aw > 0.7f*s;
    signed char q = nz ? (w>0.f?1:-1) : 0;
    float r = nz ? fabsf(aw - s) : aw;
    if (!m) g_W1q[outi]=q; else g_W2q[outi]=q;
    red[threadIdx.x]=(double)r; __syncthreads();
    for(int o=128;o;o>>=1){ if(threadIdx.x<o) red[threadIdx.x]+=red[threadIdx.x+o]; __syncthreads(); }
    if (!threadIdx.x) atomicAdd(&g_res[m], red[0]);
}

// ---------------- k_route ----------------
__global__ void k_route(const int* __restrict__ op, const int* __restrict__ a,
                        const int* __restrict__ b, const int* __restrict__ c,
                        float* __restrict__ outIdx){
    __shared__ float sLf[NOPS*NT], sLg[256*NT], sLh[256*NT], sLc[NT], sLb[NT];
    __shared__ float sP[NT]; __shared__ int sC[NT];
    int tid = threadIdx.x;
    int lane = tid & 31;
    for (int i=tid;i<256*NT;i+=256){ sLg[i]=g_Lg[i]; sLh[i]=g_Lh[i]; }
    for (int i=tid;i<NOPS*NT;i+=256) sLf[i]=g_Lf[i];
    if (tid<NT){ sLc[tid]=g_Lc[tid]; sLb[tid]=g_Lb[tid]; sP[tid]=0.f; sC[tid]=0; }
    __syncthreads();
    int i = blockIdx.x*256+tid;
    int opv=op[i], av=a[i], bv=b[i]; float cv=(float)c[i];
    float l[NT]; float mx=-1e30f; int best=0;
    #pragma unroll
    for (int t=0;t<NT;t++){
        float v = sLf[opv*NT+t]+sLg[av*NT+t]+sLh[bv*NT+t]+cv*sLc[t]+sLb[t];
        l[t]=v;
        if (v>mx){mx=v;best=t;}
    }
    float den=0.f;
    #pragma unroll
    for (int t=0;t<NT;t++){ l[t]=expf(l[t]-mx); den+=l[t]; }
    float inv = 1.f/den;
    #pragma unroll
    for (int t=0;t<NT;t++){
        float v = l[t]*inv;
        #pragma unroll
        for (int o=16;o;o>>=1) v += __shfl_xor_sync(0xffffffffu, v, o);
        if (lane==0) atomicAdd(&sP[t], v);
    }
    #pragma unroll
    for (int t=0;t<NT;t++){
        unsigned bal = __ballot_sync(0xffffffffu, best==t);
        if (lane==0 && bal) atomicAdd(&sC[t], (int)__popc(bal));
    }
    g_idx[i]=(unsigned char)best; g_gate[i]=inv; outIdx[i]=(float)best;
    __syncthreads();
    if (tid<NT){
        atomicAdd(&g_cnt[tid], sC[tid]);
        atomicAdd(&g_sumP[tid], (double)sP[tid]);
    }
}

// ---------------- k_part ----------------
__global__ void k_part(){
    __shared__ int po[NT], pc[NT];
    int tid=threadIdx.x;
    if (tid==0){
        int acc=0, nb=0;
        for (int t=0;t<NT;t++){
            po[t]=acc; g_po[t]=acc;
            int cnt = g_cnt[t]; pc[t]=cnt;
            int bl = (cnt+MROWS-1)/MROWS;
            for (int bidx=0;bidx<bl;bidx++){ g_bmT[nb]=t; g_bmR[nb]=acc+bidx*MROWS; nb++; }
            acc += bl*MROWS;
        }
        g_nblocks = nb;
    }
    __syncthreads();
    for (int t=0;t<NT;t++){
        int cnt=pc[t]; int pad = ((cnt+MROWS-1)/MROWS)*MROWS;
        for (int p=cnt+tid; p<pad; p+=256) g_src[po[t]+p] = -1;
    }
}

// ---------------- k_scat: counting-sort by tile ----------------
__global__ void k_scat(){
    __shared__ int scnt[NT], sbase[NT];
    int tid=threadIdx.x;
    if (tid<NT) scnt[tid]=0;
    __syncthreads();
    int i = blockIdx.x*256+tid;
    int t = (int)g_idx[i];
    int rank = atomicAdd(&scnt[t],1);
    __syncthreads();
    if (tid<NT) sbase[tid]=atomicAdd(&g_fill[tid], scnt[tid]);
    __syncthreads();
    g_src[g_po[t]+sbase[t]+rank]=i;
}

// ---------------- k_ffn: grouped FFN + head via tf32 mma.sync ----------------
__global__ void __launch_bounds__(256,1) k_ffn(
    const int* __restrict__ op, const int* __restrict__ aIn,
    const int* __restrict__ bIn, const int* __restrict__ cIn,
    const float* __restrict__ Win, const float* __restrict__ bin,
    const float* __restrict__ Wh1, const float* __restrict__ bh1,
    const float* __restrict__ Wh2, const float* __restrict__ bh2,
    float* __restrict__ outR)
{
    extern __shared__ float sm[];
    float* sX = sm;                   // [128][SLD]
    float* sB = sm + MROWS*SLD;       // [128][SLD]
    float* sG = sm + 2*MROWS*SLD;     // [128][SLD]
    __shared__ float sGate[MROWS];
    __shared__ int   sSrc[MROWS];
    __shared__ float sWh2[512]; __shared__ float sbh1[64]; __shared__ float sbh2[8];

    int bid = blockIdx.x;
    if (bid >= g_nblocks) return;
    int t  = g_bmT[bid], r0 = g_bmR[bid];
    int tid = threadIdx.x;
    int wid = tid>>5, lane = tid&31;
    int grp = lane>>2, tq = lane&3;
    int wm = wid&3, wn = wid>>2;
    float s1 = g_s1[t], s2 = g_s2[t];

    // ---- build X tile from tables (2 threads / row) ----
    {
        int row = tid>>1, half = tid&1;
        int token = g_src[r0+row];
        if (half==0){ sSrc[row]=token; sGate[row]= (token>=0) ? g_gate[token] : 0.f; }
        const float* wc = Win + 48*DM;
        if (token>=0){
            int opv=op[token], av=aIn[token], bv=bIn[token]; float cv=(float)cIn[token];
            const float* tf=&g_Tf[opv*DM]; const float* tg=&g_Tg[av*DM]; const float* th=&g_Th[bv*DM];
            for (int d=half*64; d<half*64+64; d++){
                float x = tf[d]+tg[d]+th[d]+cv*wc[d]+bin[d];
                sX[row*SLD+d] = __uint_as_float(f2tf(x));
            }
        } else {
            for (int d=half*64; d<half*64+64; d++) sX[row*SLD+d]=0.f;
        }
    }
    for (int i=tid;i<512;i+=256) sWh2[i]=Wh2[i];
    if (tid<64) sbh1[tid]=bh1[tid];
    if (tid<8)  sbh2[tid]=bh2[tid];

    float c2[2][8][4];
    #pragma unroll
    for(int mt=0;mt<2;mt++)
        #pragma unroll
        for(int nt=0;nt<8;nt++)
            #pragma unroll
            for(int e2=0;e2<4;e2++) c2[mt][nt][e2]=0.f;

    const signed char* W1p = g_W1q + t*DFF*DM;
    const signed char* W2p = g_W2q + t*DM*DFF;

    for (int ch=0; ch<NCHUNK; ch++){
        __syncthreads();
        // load W1 chunk [128 dff rows][128 k] -> sB
        {
            const char4* src = (const char4*)(W1p + ch*128*DM);
            for (int i=tid; i<128*DM/4; i+=256){
                char4 v = src[i];
                int n = (i*4)>>7, k = (i*4)&127;
                float* dst = sB + n*SLD + k;
                dst[0]=(float)v.x; dst[1]=(float)v.y; dst[2]=(float)v.z; dst[3]=(float)v.w;
            }
        }
        __syncthreads();
        float c1[2][8][4];
        #pragma unroll
        for(int mt=0;mt<2;mt++)
            #pragma unroll
            for(int nt=0;nt<8;nt++)
                #pragma unroll
                for(int e2=0;e2<4;e2++) c1[mt][nt][e2]=0.f;
        #pragma unroll 4
        for (int kk=0;kk<16;kk++){
            uint32_t afr[2][4];
            #pragma unroll
            for (int mt=0;mt<2;mt++){
                const float* ap = sX + (wm*32+mt*16+grp)*SLD + kk*8;
                afr[mt][0]=__float_as_uint(ap[tq]);
                afr[mt][1]=__float_as_uint(ap[8*SLD+tq]);
                afr[mt][2]=__float_as_uint(ap[tq+4]);
                afr[mt][3]=__float_as_uint(ap[8*SLD+tq+4]);
            }
            #pragma unroll
            for (int nt=0;nt<8;nt++){
                const float* bp = sB + (wn*64+nt*8+grp)*SLD + kk*8;
                uint32_t bf[2];
                bf[0]=__float_as_uint(bp[tq]);
                bf[1]=__float_as_uint(bp[tq+4]);
                mma8(c1[0][nt], afr[0], bf);
                mma8(c1[1][nt], afr[1], bf);
            }
        }
        __syncthreads();
        // gelu epilogue -> sG (tf32), then load W2 chunk -> sB
        #pragma unroll
        for (int mt=0;mt<2;mt++){
            #pragma unroll
            for (int nt=0;nt<8;nt++){
                #pragma unroll
                for (int e2=0;e2<4;e2++){
                    int r = wm*32+mt*16+grp+(e2>>1)*8;
                    int cc = wn*64+nt*8+2*tq+(e2&1);
                    float v = s1*c1[mt][nt][e2];
                    float g = 0.5f*v*(1.f+tanhf(0.7978845608f*(v+0.044715f*v*v*v)));
                    sG[r*SLD+cc] = __uint_as_float(f2tf(g));
                }
            }
        }
        for (int i=tid; i<128*128/4; i+=256){
            int n = (i*4)>>7, kl = (i*4)&127;
            char4 v = *(const char4*)(W2p + n*DFF + ch*128 + kl);
            float* dst = sB + n*SLD + kl;
            dst[0]=(float)v.x; dst[1]=(float)v.y; dst[2]=(float)v.z; dst[3]=(float)v.w;
        }
        __syncthreads();
        // GEMM2 accumulate into c2
        #pragma unroll 4
        for (int kk=0;kk<16;kk++){
            uint32_t afr[2][4];
            #pragma unroll
            for (int mt=0;mt<2;mt++){
                const float* ap = sG + (wm*32+mt*16+grp)*SLD + kk*8;
                afr[mt][0]=__float_as_uint(ap[tq]);
                afr[mt][1]=__float_as_uint(ap[8*SLD+tq]);
                afr[mt][2]=__float_as_uint(ap[tq+4]);
                afr[mt][3]=__float_as_uint(ap[8*SLD+tq+4]);
            }
            #pragma unroll
            for (int nt=0;nt<8;nt++){
                const float* bp = sB + (wn*64+nt*8+grp)*SLD + kk*8;
                uint32_t bf[2];
                bf[0]=__float_as_uint(bp[tq]);
                bf[1]=__float_as_uint(bp[tq+4]);
                mma8(c2[0][nt], afr[0], bf);
                mma8(c2[1][nt], afr[1], bf);
            }
        }
    }
    __syncthreads();
    // gated output -> sX (tf32 A for head GEMM)
    #pragma unroll
    for (int mt=0;mt<2;mt++){
        #pragma unroll
        for (int nt=0;nt<8;nt++){
            #pragma unroll
            for (int e2=0;e2<4;e2++){
                int r = wm*32+mt*16+grp+(e2>>1)*8;
                int cc = wn*64+nt*8+2*tq+(e2&1);
                float v = s2*c2[mt][nt][e2]*sGate[r];
                sX[r*SLD+cc] = __uint_as_float(f2tf(v));
            }
        }
    }
    // Wh1^T -> sB[n 0..63][k 0..127]
    for (int i=tid;i<64*128;i+=256){
        int n=i>>7,k=i&127;
        sB[n*SLD+k] = __uint_as_float(f2tf(Wh1[k*64+n]));
    }
    __syncthreads();
    float c3[2][4][4];
    #pragma unroll
    for(int mt=0;mt<2;mt++)
        #pragma unroll
        for(int nt=0;nt<4;nt++)
            #pragma unroll
            for(int e2=0;e2<4;e2++) c3[mt][nt][e2]=0.f;
    #pragma unroll 4
    for (int kk=0;kk<16;kk++){
        uint32_t afr[2][4];
        #pragma unroll
        for (int mt=0;mt<2;mt++){
            const float* ap = sX + (wm*32+mt*16+grp)*SLD + kk*8;
            afr[mt][0]=__float_as_uint(ap[tq]);
            afr[mt][1]=__float_as_uint(ap[8*SLD+tq]);
            afr[mt][2]=__float_as_uint(ap[tq+4]);
            afr[mt][3]=__float_as_uint(ap[8*SLD+tq+4]);
        }
        #pragma unroll
        for (int nt=0;nt<4;nt++){
            const float* bp = sB + (wn*32+nt*8+grp)*SLD + kk*8;
            uint32_t bf[2];
            bf[0]=__float_as_uint(bp[tq]);
            bf[1]=__float_as_uint(bp[tq+4]);
            mma8(c3[0][nt], afr[0], bf);
            mma8(c3[1][nt], afr[1], bf);
        }
    }
    __syncthreads();
    // h = relu(c3 + bh1) -> sG [128][64]
    #pragma unroll
    for (int mt=0;mt<2;mt++){
        #pragma unroll
        for (int nt=0;nt<4;nt++){
            #pragma unroll
            for (int e2=0;e2<4;e2++){
                int r = wm*32+mt*16+grp+(e2>>1)*8;
                int cc = wn*32+nt*8+2*tq+(e2&1);
                float v = c3[mt][nt][e2] + sbh1[cc];
                sG[r*SLD+cc] = fmaxf(v, 0.f);
            }
        }
    }
    __syncthreads();
    // final 64->8 + sigmoid (2 threads / row)
    {
        int row = tid>>1, c0 = (tid&1)*4;
        int token = sSrc[row];
        if (token>=0){
            float acc0=sbh2[c0], acc1=sbh2[c0+1], acc2=sbh2[c0+2], acc3=sbh2[c0+3];
            #pragma unroll 8
            for (int k2=0;k2<64;k2++){
                float hv = sG[row*SLD+k2];
                acc0 += hv*sWh2[k2*8+c0];
                acc1 += hv*sWh2[k2*8+c0+1];
                acc2 += hv*sWh2[k2*8+c0+2];
                acc3 += hv*sWh2[k2*8+c0+3];
            }
            float* o = outR + (size_t)token*8 + c0;
            o[0] = 1.f/(1.f+expf(-acc0));
            o[1] = 1.f/(1.f+expf(-acc1));
            o[2] = 1.f/(1.f+expf(-acc2));
            o[3] = 1.f/(1.f+expf(-acc3));
        }
    }
}

// ---------------- k_aux ----------------
__global__ void k_aux(float* __restrict__ aux){
    if (threadIdx.x==0){
        double sp=0.0, cp[4]={0,0,0,0};
        for (int t=0;t<NT;t++){
            double frac = (double)g_cnt[t]/(double)BTOK;
            double mp = g_sumP[t]/(double)BTOK;
            sp += frac*mp;
            cp[t>>2] += mp;
        }
        double sparsity = 16.0*sp;
        double tern = g_res[0]/1048576.0 + g_res[1]/1048576.0;
        double divv = 0.0;
        for (int i=0;i<4;i++) divv += cp[i]*log(cp[i]+1e-9);
        aux[0] = (float)(0.01*tern + 0.005*sparsity + 0.01*divv);
    }
}

// ---------------- launch ----------------
extern "C" void kernel_launch(void* const* d_in, const int* in_sizes, int n_in,
                              void* d_out, int out_size){
    const int *op=nullptr,*a=nullptr,*b=nullptr,*c=nullptr;
    const float *oe=nullptr,*Win=nullptr,*bin=nullptr,*Wr=nullptr,*W1=nullptr,*W2=nullptr;
    const float *Wh1=nullptr,*bh1=nullptr,*Wh2=nullptr,*bh2=nullptr;
    int nb_=0, nw=0;
    for (int i=0;i<n_in;i++){
        int s = in_sizes[i]; void* p = (void*)d_in[i];
        switch(s){
            case BTOK:
                if(nb_==0) op=(const int*)p; else if(nb_==1) a=(const int*)p;
                else if(nb_==2) b=(const int*)p; else c=(const int*)p;
                nb_++; break;
            case 256:  oe=(const float*)p; break;
            case 6272: Win=(const float*)p; break;
            case 128:  bin=(const float*)p; break;
            case 2048: Wr=(const float*)p; break;
            case 1048576: if(nw==0) W1=(const float*)p; else W2=(const float*)p; nw++; break;
            case 8192: Wh1=(const float*)p; break;
            case 64:   bh1=(const float*)p; break;
            case 512:  Wh2=(const float*)p; break;
            case 8:    bh2=(const float*)p; break;
            default: break;
        }
    }
    float* out = (float*)d_out;
    int smem = 3*MROWS*SLD*4;
    cudaFuncSetAttribute(k_ffn, cudaFuncAttributeMaxDynamicSharedMemorySize, smem);

    k_init<<<1,32>>>();
    k_tables<<<260,256>>>(oe,Win);
    k_lt<<<33,256>>>(Wr,Win,bin);
    k_scale<<<32,256>>>(W1,W2);
    k_quant<<<8192,256>>>(W1,W2);
    k_route<<<BTOK/256,256>>>(op,a,b,c,out + (size_t)BTOK*8);
    k_part<<<1,256>>>();
    k_scat<<<BTOK/256,256>>>();
    k_ffn<<<MAXBLK,256,smem>>>(op,a,b,c,Win,bin,Wh1,bh1,Wh2,bh2,out);
    k_aux<<<1,32>>>(out + (size_t)BTOK*9);
}

// round 3
// speedup vs baseline: 1.0847x; 1.0847x over previous
#include <cuda_runtime.h>
#include <cuda_bf16.h>
#include <cstdint>

#define BTOK 262144
#define DM 128
#define DFF 512
#define NT 16
#define NOPS 8
#define EMB 32
#define MROWS 128
#define NCHUNK 4
#define SLD 132
#define MAXBLK (BTOK/MROWS + NT)
#define PADB (BTOK + NT*MROWS)

// ---------------- device scratch (no allocation allowed) ----------------
__device__ float g_Tf[NOPS*DM];
__device__ float g_Tg[256*DM];
__device__ float g_Th[256*DM];
__device__ float g_Lf[NOPS*NT];
__device__ float g_Lg[256*NT];
__device__ float g_Lh[256*NT];
__device__ float g_Lc[NT];
__device__ float g_Lb[NT];
__device__ float g_s1[NT], g_s2[NT];
__device__ double g_sabs[32];
__device__ double g_res[2];
__device__ signed char g_W1q[NT*DFF*DM];   // [t][n(dff)][k(d)]
__device__ signed char g_W2q[NT*DM*DFF];   // [t][n(d)][k(dff)]
__device__ int g_cnt[NT];
__device__ double g_sumP[NT];
__device__ int g_fill[NT];
__device__ int g_po[NT];
__device__ int g_nblocks;
__device__ unsigned char g_idx[BTOK];
__device__ float g_gate[BTOK];
__device__ int g_src[PADB];
__device__ int g_bmT[MAXBLK];
__device__ int g_bmR[MAXBLK];

// ---------------- helpers ----------------
__device__ __forceinline__ uint32_t f2tf(float v){
    uint32_t r; asm("cvt.rna.tf32.f32 %0, %1;" : "=r"(r) : "f"(v)); return r;
}
__device__ __forceinline__ float tanh_fast(float v){
    float r; asm("tanh.approx.f32 %0, %1;" : "=f"(r) : "f"(v)); return r;
}
__device__ __forceinline__ void mma8(float* c, const uint32_t* a, const uint32_t* b){
    asm volatile("mma.sync.aligned.m16n8k8.row.col.f32.tf32.tf32.f32 "
        "{%0,%1,%2,%3},{%4,%5,%6,%7},{%8,%9},{%0,%1,%2,%3};"
        : "+f"(c[0]),"+f"(c[1]),"+f"(c[2]),"+f"(c[3])
        : "r"(a[0]),"r"(a[1]),"r"(a[2]),"r"(a[3]),"r"(b[0]),"r"(b[1]));
}

// ---------------- k_init ----------------
__global__ void k_init(){
    int i = threadIdx.x;
    if (i < NT){ g_cnt[i]=0; g_sumP[i]=0.0; g_fill[i]=0; }
    if (i < 32) g_sabs[i]=0.0;
    if (i < 2)  g_res[i]=0.0;
}

// ---------------- k_tables: feature tables ----------------
__global__ void k_tables(const float* __restrict__ oe, const float* __restrict__ Win){
    int gid = blockIdx.x*256 + threadIdx.x;
    if (gid < 32768){
        int av = gid >> 7, d = gid & 127;
        float s = 0.f;
        #pragma unroll
        for (int i=0;i<8;i++) if ((av>>i)&1) s += Win[(32+i)*DM + d];
        g_Tg[av*DM+d] = s;
    } else if (gid < 65536){
        int g2 = gid - 32768;
        int bv = g2 >> 7, d = g2 & 127;
        float s = 0.f;
        #pragma unroll
        for (int i=0;i<8;i++) if ((bv>>i)&1) s += Win[(40+i)*DM + d];
        g_Th[bv*DM+d] = s;
    } else if (gid < 66560){
        int g2 = gid - 65536;
        int op = g2 >> 7, d = g2 & 127;
        float s = 0.f;
        #pragma unroll
        for (int j=0;j<EMB;j++) s += oe[op*EMB+j]*Win[j*DM+d];
        g_Tf[op*DM+d] = s;
    }
}

// ---------------- k_lt: router logit tables ----------------
__global__ void k_lt(const float* __restrict__ Wr, const float* __restrict__ Win,
                     const float* __restrict__ bin){
    int gid = blockIdx.x*256+threadIdx.x;
    if (gid < 4096){
        int av=gid>>4, t=gid&15; float s=0.f;
        for(int d=0;d<DM;d++) s += g_Tg[av*DM+d]*Wr[d*NT+t];
        g_Lg[gid]=s;
    } else if (gid < 8192){
        int g2=gid-4096; int bv=g2>>4,t=g2&15; float s=0.f;
        for(int d=0;d<DM;d++) s += g_Th[bv*DM+d]*Wr[d*NT+t];
        g_Lh[g2]=s;
    } else if (gid < 8320){
        int g2=gid-8192; int op=g2>>4,t=g2&15; float s=0.f;
        for(int d=0;d<DM;d++) s += g_Tf[op*DM+d]*Wr[d*NT+t];
        g_Lf[g2]=s;
    } else if (gid < 8336){
        int t=gid-8320; float s=0.f;
        for(int d=0;d<DM;d++) s += Win[48*DM+d]*Wr[d*NT+t];
        g_Lc[t]=s;
    } else if (gid < 8352){
        int t=gid-8336; float s=0.f;
        for(int d=0;d<DM;d++) s += bin[d]*Wr[d*NT+t];
        g_Lb[t]=s;
    }
}

// ---------------- k_scalep: partial |W| sums, 512 blocks ----------------
__global__ void k_scalep(const float* __restrict__ W1, const float* __restrict__ W2){
    __shared__ double red[256];
    int tile = blockIdx.x >> 4;          // 0..31
    int sub  = blockIdx.x & 15;
    const float* W = (tile < 16 ? W1 + tile*65536 : W2 + (tile-16)*65536) + sub*4096;
    const float4* W4 = (const float4*)W;
    double s = 0.0;
    #pragma unroll
    for (int r=0;r<4;r++){
        float4 v = W4[threadIdx.x + r*256];
        s += (double)(fabsf(v.x)+fabsf(v.y)+fabsf(v.z)+fabsf(v.w));
    }
    red[threadIdx.x]=s; __syncthreads();
    for (int o=128;o;o>>=1){ if(threadIdx.x<o) red[threadIdx.x]+=red[threadIdx.x+o]; __syncthreads(); }
    if (!threadIdx.x) atomicAdd(&g_sabs[tile], red[0]);
}

// ---------------- k_sfin ----------------
__global__ void k_sfin(){
    int t = threadIdx.x;
    if (t < 16) g_s1[t] = (float)(g_sabs[t]/65536.0);
    else if (t < 32) g_s2[t-16] = (float)(g_sabs[t]/65536.0);
}

// ---------------- k_quant: ternary signs (transposed) + residual ----------------
__global__ void k_quant(const float* __restrict__ W1, const float* __restrict__ W2){
    __shared__ double red[256];
    int gid = blockIdx.x*256+threadIdx.x;
    int m = gid >> 20;
    int e = gid & 0xFFFFF;
    int t = e >> 16, j = e & 0xFFFF;
    float w, s; int outi;
    if (!m){ w = W1[e]; s = g_s1[t]; int k=j>>9, n=j&511; outi = t*65536 + n*128 + k; }
    else   { w = W2[e]; s = g_s2[t]; int kk=j>>7, nn=j&127; outi = t*65536 + nn*512 + kk; }
    float aw = fabsf(w);
    bool nz = aw > 0.7f*s;
    signed char q = nz ? (w>0.f?1:-1) : 0;
    float r = nz ? fabsf(aw - s) : aw;
    if (!m) g_W1q[outi]=q; else g_W2q[outi]=q;
    red[threadIdx.x]=(double)r; __syncthreads();
    for(int o=128;o;o>>=1){ if(threadIdx.x<o) red[threadIdx.x]+=red[threadIdx.x+o]; __syncthreads(); }
    if (!threadIdx.x) atomicAdd(&g_res[m], red[0]);
}

// ---------------- k_route ----------------
__global__ void k_route(const int* __restrict__ op, const int* __restrict__ a,
                        const int* __restrict__ b, const int* __restrict__ c,
                        float* __restrict__ outIdx){
    __shared__ float sLf[NOPS*NT], sLg[256*NT], sLh[256*NT], sLc[NT], sLb[NT];
    __shared__ float sP[NT]; __shared__ int sC[NT];
    int tid = threadIdx.x;
    int lane = tid & 31;
    for (int i=tid;i<256*NT;i+=256){ sLg[i]=g_Lg[i]; sLh[i]=g_Lh[i]; }
    for (int i=tid;i<NOPS*NT;i+=256) sLf[i]=g_Lf[i];
    if (tid<NT){ sLc[tid]=g_Lc[tid]; sLb[tid]=g_Lb[tid]; sP[tid]=0.f; sC[tid]=0; }
    __syncthreads();
    int i = blockIdx.x*256+tid;
    int opv=op[i], av=a[i], bv=b[i]; float cv=(float)c[i];
    float l[NT]; float mx=-1e30f; int best=0;
    #pragma unroll
    for (int t=0;t<NT;t++){
        float v = sLf[opv*NT+t]+sLg[av*NT+t]+sLh[bv*NT+t]+cv*sLc[t]+sLb[t];
        l[t]=v;
        if (v>mx){mx=v;best=t;}
    }
    float den=0.f;
    #pragma unroll
    for (int t=0;t<NT;t++){ l[t]=__expf(l[t]-mx); den+=l[t]; }
    float inv = 1.f/den;
    #pragma unroll
    for (int t=0;t<NT;t++){
        float v = l[t]*inv;
        #pragma unroll
        for (int o=16;o;o>>=1) v += __shfl_xor_sync(0xffffffffu, v, o);
        if (lane==0) atomicAdd(&sP[t], v);
    }
    #pragma unroll
    for (int t=0;t<NT;t++){
        unsigned bal = __ballot_sync(0xffffffffu, best==t);
        if (lane==0 && bal) atomicAdd(&sC[t], (int)__popc(bal));
    }
    g_idx[i]=(unsigned char)best; g_gate[i]=inv; outIdx[i]=(float)best;
    __syncthreads();
    if (tid<NT){
        atomicAdd(&g_cnt[tid], sC[tid]);
        atomicAdd(&g_sumP[tid], (double)sP[tid]);
    }
}

// ---------------- k_part ----------------
__global__ void k_part(){
    __shared__ int po[NT], pc[NT];
    int tid=threadIdx.x;
    if (tid==0){
        int acc=0, nb=0;
        for (int t=0;t<NT;t++){
            po[t]=acc; g_po[t]=acc;
            int cnt = g_cnt[t]; pc[t]=cnt;
            int bl = (cnt+MROWS-1)/MROWS;
            for (int bidx=0;bidx<bl;bidx++){ g_bmT[nb]=t; g_bmR[nb]=acc+bidx*MROWS; nb++; }
            acc += bl*MROWS;
        }
        g_nblocks = nb;
    }
    __syncthreads();
    for (int t=0;t<NT;t++){
        int cnt=pc[t]; int pad = ((cnt+MROWS-1)/MROWS)*MROWS;
        for (int p=cnt+tid; p<pad; p+=256) g_src[po[t]+p] = -1;
    }
}

// ---------------- k_scat ----------------
__global__ void k_scat(){
    __shared__ int scnt[NT], sbase[NT];
    int tid=threadIdx.x;
    if (tid<NT) scnt[tid]=0;
    __syncthreads();
    int i = blockIdx.x*256+tid;
    int t = (int)g_idx[i];
    int rank = atomicAdd(&scnt[t],1);
    __syncthreads();
    if (tid<NT) sbase[tid]=atomicAdd(&g_fill[tid], scnt[tid]);
    __syncthreads();
    g_src[g_po[t]+sbase[t]+rank]=i;
}

// ---------------- k_ffn: 512 threads, grouped FFN + head via tf32 mma ----------------
__global__ void __launch_bounds__(512,1) k_ffn(
    const int* __restrict__ op, const int* __restrict__ aIn,
    const int* __restrict__ bIn, const int* __restrict__ cIn,
    const float* __restrict__ Win, const float* __restrict__ bin,
    const float* __restrict__ Wh1, const float* __restrict__ bh1,
    const float* __restrict__ Wh2, const float* __restrict__ bh2,
    float* __restrict__ outR)
{
    extern __shared__ float sm[];
    float* sX = sm;                   // [128][SLD]
    float* sB = sm + MROWS*SLD;       // [128][SLD]
    float* sG = sm + 2*MROWS*SLD;     // [128][SLD]
    __shared__ float sGate[MROWS];
    __shared__ int   sSrc[MROWS];
    __shared__ float sWh2[512]; __shared__ float sbh1[64]; __shared__ float sbh2[8];

    int bid = blockIdx.x;
    if (bid >= g_nblocks) return;
    int t  = g_bmT[bid], r0 = g_bmR[bid];
    int tid = threadIdx.x;
    int wid = tid>>5, lane = tid&31;
    int grp = lane>>2, tq = lane&3;
    int wm = wid&3, wn = wid>>2;       // 4x4 warp grid, 32x32 tiles
    float s1 = g_s1[t], s2 = g_s2[t];

    // ---- build X tile from tables (4 threads / row) ----
    {
        int row = tid>>2, q = tid&3;
        int token = g_src[r0+row];
        if (q==0){ sSrc[row]=token; sGate[row]= (token>=0) ? g_gate[token] : 0.f; }
        const float* wc = Win + 48*DM;
        if (token>=0){
            int opv=op[token], av=aIn[token], bv=bIn[token]; float cv=(float)cIn[token];
            const float* tf=&g_Tf[opv*DM]; const float* tg=&g_Tg[av*DM]; const float* th=&g_Th[bv*DM];
            #pragma unroll 8
            for (int d=q*32; d<q*32+32; d++){
                float x = tf[d]+tg[d]+th[d]+cv*wc[d]+bin[d];
                sX[row*SLD+d] = __uint_as_float(f2tf(x));
            }
        } else {
            for (int d=q*32; d<q*32+32; d++) sX[row*SLD+d]=0.f;
        }
    }
    if (tid<512) sWh2[tid]=Wh2[tid];
    if (tid<64) sbh1[tid]=bh1[tid];
    if (tid<8)  sbh2[tid]=bh2[tid];

    float c2[2][4][4];
    #pragma unroll
    for(int mt=0;mt<2;mt++)
        #pragma unroll
        for(int nt=0;nt<4;nt++)
            #pragma unroll
            for(int e2=0;e2<4;e2++) c2[mt][nt][e2]=0.f;

    const signed char* W1p = g_W1q + t*DFF*DM;
    const signed char* W2p = g_W2q + t*DM*DFF;

    for (int ch=0; ch<NCHUNK; ch++){
        __syncthreads();
        // load W1 chunk [128 dff rows][128 k] -> sB
        {
            const char4* src = (const char4*)(W1p + ch*128*DM);
            #pragma unroll
            for (int r=0;r<8;r++){
                int i = tid + r*512;
                char4 v = src[i];
                int n = (i*4)>>7, k = (i*4)&127;
                float* dst = sB + n*SLD + k;
                dst[0]=(float)v.x; dst[1]=(float)v.y; dst[2]=(float)v.z; dst[3]=(float)v.w;
            }
        }
        __syncthreads();
        float c1[2][4][4];
        #pragma unroll
        for(int mt=0;mt<2;mt++)
            #pragma unroll
            for(int nt=0;nt<4;nt++)
                #pragma unroll
                for(int e2=0;e2<4;e2++) c1[mt][nt][e2]=0.f;
        #pragma unroll 4
        for (int kk=0;kk<16;kk++){
            uint32_t afr[2][4];
            #pragma unroll
            for (int mt=0;mt<2;mt++){
                const float* ap = sX + (wm*32+mt*16+grp)*SLD + kk*8;
                afr[mt][0]=__float_as_uint(ap[tq]);
                afr[mt][1]=__float_as_uint(ap[8*SLD+tq]);
                afr[mt][2]=__float_as_uint(ap[tq+4]);
                afr[mt][3]=__float_as_uint(ap[8*SLD+tq+4]);
            }
            #pragma unroll
            for (int nt=0;nt<4;nt++){
                const float* bp = sB + (wn*32+nt*8+grp)*SLD + kk*8;
                uint32_t bf[2];
                bf[0]=__float_as_uint(bp[tq]);
                bf[1]=__float_as_uint(bp[tq+4]);
                mma8(c1[0][nt], afr[0], bf);
                mma8(c1[1][nt], afr[1], bf);
            }
        }
        __syncthreads();
        // gelu epilogue -> sG (tf32), then load W2 chunk -> sB
        #pragma unroll
        for (int mt=0;mt<2;mt++){
            #pragma unroll
            for (int nt=0;nt<4;nt++){
                #pragma unroll
                for (int e2=0;e2<4;e2++){
                    int r = wm*32+mt*16+grp+(e2>>1)*8;
                    int cc = wn*32+nt*8+2*tq+(e2&1);
                    float v = s1*c1[mt][nt][e2];
                    float g = 0.5f*v*(1.f+tanh_fast(0.7978845608f*(v+0.044715f*v*v*v)));
                    sG[r*SLD+cc] = __uint_as_float(f2tf(g));
                }
            }
        }
        #pragma unroll
        for (int r=0;r<8;r++){
            int i = tid + r*512;
            int n = (i*4)>>7, kl = (i*4)&127;
            char4 v = *(const char4*)(W2p + n*DFF + ch*128 + kl);
            float* dst = sB + n*SLD + kl;
            dst[0]=(float)v.x; dst[1]=(float)v.y; dst[2]=(float)v.z; dst[3]=(float)v.w;
        }
        __syncthreads();
        // GEMM2 accumulate into c2
        #pragma unroll 4
        for (int kk=0;kk<16;kk++){
            uint32_t afr[2][4];
            #pragma unroll
            for (int mt=0;mt<2;mt++){
                const float* ap = sG + (wm*32+mt*16+grp)*SLD + kk*8;
                afr[mt][0]=__float_as_uint(ap[tq]);
                afr[mt][1]=__float_as_uint(ap[8*SLD+tq]);
                afr[mt][2]=__float_as_uint(ap[tq+4]);
                afr[mt][3]=__float_as_uint(ap[8*SLD+tq+4]);
            }
            #pragma unroll
            for (int nt=0;nt<4;nt++){
                const float* bp = sB + (wn*32+nt*8+grp)*SLD + kk*8;
                uint32_t bf[2];
                bf[0]=__float_as_uint(bp[tq]);
                bf[1]=__float_as_uint(bp[tq+4]);
                mma8(c2[0][nt], afr[0], bf);
                mma8(c2[1][nt], afr[1], bf);
            }
        }
    }
    __syncthreads();
    // gated output -> sX (tf32 A for head GEMM)
    #pragma unroll
    for (int mt=0;mt<2;mt++){
        #pragma unroll
        for (int nt=0;nt<4;nt++){
            #pragma unroll
            for (int e2=0;e2<4;e2++){
                int r = wm*32+mt*16+grp+(e2>>1)*8;
                int cc = wn*32+nt*8+2*tq+(e2&1);
                float v = s2*c2[mt][nt][e2]*sGate[r];
                sX[r*SLD+cc] = __uint_as_float(f2tf(v));
            }
        }
    }
    // Wh1^T -> sB[n 0..63][k 0..127]
    for (int i=tid;i<64*128;i+=512){
        int n=i>>7,k=i&127;
        sB[n*SLD+k] = __uint_as_float(f2tf(Wh1[k*64+n]));
    }
    __syncthreads();
    float c3[2][2][4];
    #pragma unroll
    for(int mt=0;mt<2;mt++)
        #pragma unroll
        for(int nt=0;nt<2;nt++)
            #pragma unroll
            for(int e2=0;e2<4;e2++) c3[mt][nt][e2]=0.f;
    #pragma unroll 4
    for (int kk=0;kk<16;kk++){
        uint32_t afr[2][4];
        #pragma unroll
        for (int mt=0;mt<2;mt++){
            const float* ap = sX + (wm*32+mt*16+grp)*SLD + kk*8;
            afr[mt][0]=__float_as_uint(ap[tq]);
            afr[mt][1]=__float_as_uint(ap[8*SLD+tq]);
            afr[mt][2]=__float_as_uint(ap[tq+4]);
            afr[mt][3]=__float_as_uint(ap[8*SLD+tq+4]);
        }
        #pragma unroll
        for (int nt=0;nt<2;nt++){
            const float* bp = sB + (wn*16+nt*8+grp)*SLD + kk*8;
            uint32_t bf[2];
            bf[0]=__float_as_uint(bp[tq]);
            bf[1]=__float_as_uint(bp[tq+4]);
            mma8(c3[0][nt], afr[0], bf);
            mma8(c3[1][nt], afr[1], bf);
        }
    }
    __syncthreads();
    // h = relu(c3 + bh1) -> sG [128][64]
    #pragma unroll
    for (int mt=0;mt<2;mt++){
        #pragma unroll
        for (int nt=0;nt<2;nt++){
            #pragma unroll
            for (int e2=0;e2<4;e2++){
                int r = wm*32+mt*16+grp+(e2>>1)*8;
                int cc = wn*16+nt*8+2*tq+(e2&1);
                float v = c3[mt][nt][e2] + sbh1[cc];
                sG[r*SLD+cc] = fmaxf(v, 0.f);
            }
        }
    }
    __syncthreads();
    // final 64->8 + sigmoid (4 threads / row, 2 outputs each)
    {
        int row = tid>>2, c0 = (tid&3)*2;
        int token = sSrc[row];
        if (token>=0){
            float acc0=sbh2[c0], acc1=sbh2[c0+1];
            #pragma unroll 16
            for (int k2=0;k2<64;k2++){
                float hv = sG[row*SLD+k2];
                acc0 += hv*sWh2[k2*8+c0];
                acc1 += hv*sWh2[k2*8+c0+1];
            }
            float* o = outR + (size_t)token*8 + c0;
            o[0] = 1.f/(1.f+__expf(-acc0));
            o[1] = 1.f/(1.f+__expf(-acc1));
        }
    }
}

// ---------------- k_aux ----------------
__global__ void k_aux(float* __restrict__ aux){
    if (threadIdx.x==0){
        double sp=0.0, cp[4]={0,0,0,0};
        for (int t=0;t<NT;t++){
            double frac = (double)g_cnt[t]/(double)BTOK;
            double mp = g_sumP[t]/(double)BTOK;
            sp += frac*mp;
            cp[t>>2] += mp;
        }
        double sparsity = 16.0*sp;
        double tern = g_res[0]/1048576.0 + g_res[1]/1048576.0;
        double divv = 0.0;
        for (int i=0;i<4;i++) divv += cp[i]*log(cp[i]+1e-9);
        aux[0] = (float)(0.01*tern + 0.005*sparsity + 0.01*divv);
    }
}

// ---------------- launch ----------------
extern "C" void kernel_launch(void* const* d_in, const int* in_sizes, int n_in,
                              void* d_out, int out_size){
    const int *op=nullptr,*a=nullptr,*b=nullptr,*c=nullptr;
    const float *oe=nullptr,*Win=nullptr,*bin=nullptr,*Wr=nullptr,*W1=nullptr,*W2=nullptr;
    const float *Wh1=nullptr,*bh1=nullptr,*Wh2=nullptr,*bh2=nullptr;
    int nb_=0, nw=0;
    for (int i=0;i<n_in;i++){
        int s = in_sizes[i]; void* p = (void*)d_in[i];
        switch(s){
            case BTOK:
                if(nb_==0) op=(const int*)p; else if(nb_==1) a=(const int*)p;
                else if(nb_==2) b=(const int*)p; else c=(const int*)p;
                nb_++; break;
            case 256:  oe=(const float*)p; break;
            case 6272: Win=(const float*)p; break;
            case 128:  bin=(const float*)p; break;
            case 2048: Wr=(const float*)p; break;
            case 1048576: if(nw==0) W1=(const float*)p; else W2=(const float*)p; nw++; break;
            case 8192: Wh1=(const float*)p; break;
            case 64:   bh1=(const float*)p; break;
            case 512:  Wh2=(const float*)p; break;
            case 8:    bh2=(const float*)p; break;
            default: break;
        }
    }
    float* out = (float*)d_out;
    int smem = 3*MROWS*SLD*4;
    cudaFuncSetAttribute(k_ffn, cudaFuncAttributeMaxDynamicSharedMemorySize, smem);

    k_init<<<1,32>>>();
    k_tables<<<260,256>>>(oe,Win);
    k_lt<<<33,256>>>(Wr,Win,bin);
    k_scalep<<<512,256>>>(W1,W2);
    k_sfin<<<1,32>>>();
    k_quant<<<8192,256>>>(W1,W2);
    k_route<<<BTOK/256,256>>>(op,a,b,c,out + (size_t)BTOK*8);
    k_part<<<1,256>>>();
    k_scat<<<BTOK/256,256>>>();
    k_ffn<<<MAXBLK,512,smem>>>(op,a,b,c,Win,bin,Wh1,bh1,Wh2,bh2,out);
    k_aux<<<1,32>>>(out + (size_t)BTOK*9);
}

// round 5
// speedup vs baseline: 1.4599x; 1.3459x over previous
#include <cuda_runtime.h>
#include <cuda_fp16.h>
#include <cstdint>

#define BTOK 262144
#define DM 128
#define DFF 512
#define NT 16
#define NOPS 8
#define EMB 32
#define MROWS 128
#define SLDH 136
#define MAXBLK (BTOK/MROWS + NT)
#define PADB (BTOK + NT*MROWS)

// ---------------- device scratch ----------------
__device__ float g_Tf[NOPS*DM];
__device__ float g_Tg[256*DM];
__device__ float g_Th[256*DM];
__device__ float g_Lf[NOPS*NT];
__device__ float g_Lg[256*NT];
__device__ float g_Lh[256*NT];
__device__ float g_Lc[NT];
__device__ float g_Lb[NT];
__device__ float g_s1[NT], g_s2[NT];
__device__ double g_sabs[32];
__device__ double g_res[2];
__device__ signed char g_W1q[NT*DFF*DM];   // [t][n(dff)][k(d)]
__device__ signed char g_W2q[NT*DM*DFF];   // [t][n(d)][k(dff)]
__device__ int g_cnt[NT];
__device__ double g_sumP[NT];
__device__ int g_fill[NT];
__device__ int g_po[NT];
__device__ int g_nblocks;
__device__ unsigned char g_idx[BTOK];
__device__ float g_gate[BTOK];
__device__ int g_src[PADB];
__device__ int g_bmT[MAXBLK];
__device__ int g_bmR[MAXBLK];

// ---------------- helpers ----------------
__device__ __forceinline__ float tanh_fast(float v){
    float r; asm("tanh.approx.f32 %0, %1;" : "=f"(r) : "f"(v)); return r;
}
__device__ __forceinline__ uint32_t smem_u32(const void* p){
    uint32_t a;
    asm("{ .reg .u64 t; cvta.to.shared.u64 t, %1; cvt.u32.u64 %0, t; }":"=r"(a):"l"(p));
    return a;
}
__device__ __forceinline__ void ldsm4(uint32_t* r, uint32_t addr){
    asm volatile("ldmatrix.sync.aligned.m8n8.x4.shared.b16 {%0,%1,%2,%3}, [%4];"
        : "=r"(r[0]),"=r"(r[1]),"=r"(r[2]),"=r"(r[3]) : "r"(addr));
}
__device__ __forceinline__ void ldsm2(uint32_t* r, uint32_t addr){
    asm volatile("ldmatrix.sync.aligned.m8n8.x2.shared.b16 {%0,%1}, [%2];"
        : "=r"(r[0]),"=r"(r[1]) : "r"(addr));
}
__device__ __forceinline__ void mma16(float* c, const uint32_t* a, const uint32_t* b){
    asm volatile("mma.sync.aligned.m16n8k16.row.col.f32.f16.f16.f32 "
        "{%0,%1,%2,%3},{%4,%5,%6,%7},{%8,%9},{%0,%1,%2,%3};"
        : "+f"(c[0]),"+f"(c[1]),"+f"(c[2]),"+f"(c[3])
        : "r"(a[0]),"r"(a[1]),"r"(a[2]),"r"(a[3]),"r"(b[0]),"r"(b[1]));
}
__device__ __forceinline__ __half2 h2pack(float a, float b){
    return __floats2half2_rn(a, b);
}

// ---------------- k_init ----------------
__global__ void k_init(){
    int i = threadIdx.x;
    if (i < NT){ g_cnt[i]=0; g_sumP[i]=0.0; g_fill[i]=0; }
    if (i < 32) g_sabs[i]=0.0;
    if (i < 2)  g_res[i]=0.0;
}

// ---------------- k_tables ----------------
__global__ void k_tables(const float* __restrict__ oe, const float* __restrict__ Win){
    int gid = blockIdx.x*256 + threadIdx.x;
    if (gid < 32768){
        int av = gid >> 7, d = gid & 127;
        float s = 0.f;
        #pragma unroll
        for (int i=0;i<8;i++) if ((av>>i)&1) s += Win[(32+i)*DM + d];
        g_Tg[av*DM+d] = s;
    } else if (gid < 65536){
        int g2 = gid - 32768;
        int bv = g2 >> 7, d = g2 & 127;
        float s = 0.f;
        #pragma unroll
        for (int i=0;i<8;i++) if ((bv>>i)&1) s += Win[(40+i)*DM + d];
        g_Th[bv*DM+d] = s;
    } else if (gid < 66560){
        int g2 = gid - 65536;
        int op = g2 >> 7, d = g2 & 127;
        float s = 0.f;
        #pragma unroll
        for (int j=0;j<EMB;j++) s += oe[op*EMB+j]*Win[j*DM+d];
        g_Tf[op*DM+d] = s;
    }
}

// ---------------- k_lt ----------------
__global__ void k_lt(const float* __restrict__ Wr, const float* __restrict__ Win,
                     const float* __restrict__ bin){
    int gid = blockIdx.x*256+threadIdx.x;
    if (gid < 4096){
        int av=gid>>4, t=gid&15; float s=0.f;
        for(int d=0;d<DM;d++) s += g_Tg[av*DM+d]*Wr[d*NT+t];
        g_Lg[gid]=s;
    } else if (gid < 8192){
        int g2=gid-4096; int bv=g2>>4,t=g2&15; float s=0.f;
        for(int d=0;d<DM;d++) s += g_Th[bv*DM+d]*Wr[d*NT+t];
        g_Lh[g2]=s;
    } else if (gid < 8320){
        int g2=gid-8192; int op=g2>>4,t=g2&15; float s=0.f;
        for(int d=0;d<DM;d++) s += g_Tf[op*DM+d]*Wr[d*NT+t];
        g_Lf[g2]=s;
    } else if (gid < 8336){
        int t=gid-8320; float s=0.f;
        for(int d=0;d<DM;d++) s += Win[48*DM+d]*Wr[d*NT+t];
        g_Lc[t]=s;
    } else if (gid < 8352){
        int t=gid-8336; float s=0.f;
        for(int d=0;d<DM;d++) s += bin[d]*Wr[d*NT+t];
        g_Lb[t]=s;
    }
}

// ---------------- k_scalep ----------------
__global__ void k_scalep(const float* __restrict__ W1, const float* __restrict__ W2){
    __shared__ double red[256];
    int tile = blockIdx.x >> 4;
    int sub  = blockIdx.x & 15;
    const float* W = (tile < 16 ? W1 + tile*65536 : W2 + (tile-16)*65536) + sub*4096;
    const float4* W4 = (const float4*)W;
    double s = 0.0;
    #pragma unroll
    for (int r=0;r<4;r++){
        float4 v = W4[threadIdx.x + r*256];
        s += (double)(fabsf(v.x)+fabsf(v.y)+fabsf(v.z)+fabsf(v.w));
    }
    red[threadIdx.x]=s; __syncthreads();
    for (int o=128;o;o>>=1){ if(threadIdx.x<o) red[threadIdx.x]+=red[threadIdx.x+o]; __syncthreads(); }
    if (!threadIdx.x) atomicAdd(&g_sabs[tile], red[0]);
}

// ---------------- k_sfin ----------------
__global__ void k_sfin(){
    int t = threadIdx.x;
    if (t < 16) g_s1[t] = (float)(g_sabs[t]/65536.0);
    else if (t < 32) g_s2[t-16] = (float)(g_sabs[t]/65536.0);
}

// ---------------- k_quant ----------------
__global__ void k_quant(const float* __restrict__ W1, const float* __restrict__ W2){
    __shared__ double red[256];
    int gid = blockIdx.x*256+threadIdx.x;
    int m = gid >> 20;
    int e = gid & 0xFFFFF;
    int t = e >> 16, j = e & 0xFFFF;
    float w, s; int outi;
    if (!m){ w = W1[e]; s = g_s1[t]; int k=j>>9, n=j&511; outi = t*65536 + n*128 + k; }
    else   { w = W2[e]; s = g_s2[t]; int kk=j>>7, nn=j&127; outi = t*65536 + nn*512 + kk; }
    float aw = fabsf(w);
    bool nz = aw > 0.7f*s;
    signed char q = nz ? (w>0.f?1:-1) : 0;
    float r = nz ? fabsf(aw - s) : aw;
    if (!m) g_W1q[outi]=q; else g_W2q[outi]=q;
    red[threadIdx.x]=(double)r; __syncthreads();
    for(int o=128;o;o>>=1){ if(threadIdx.x<o) red[threadIdx.x]+=red[threadIdx.x+o]; __syncthreads(); }
    if (!threadIdx.x) atomicAdd(&g_res[m], red[0]);
}

// ---------------- k_route ----------------
__global__ void k_route(const int* __restrict__ op, const int* __restrict__ a,
                        const int* __restrict__ b, const int* __restrict__ c,
                        float* __restrict__ outIdx){
    __shared__ float sLf[NOPS*NT], sLg[256*NT], sLh[256*NT], sLc[NT], sLb[NT];
    __shared__ float sP[NT]; __shared__ int sC[NT];
    int tid = threadIdx.x;
    int lane = tid & 31;
    for (int i=tid;i<256*NT;i+=256){ sLg[i]=g_Lg[i]; sLh[i]=g_Lh[i]; }
    for (int i=tid;i<NOPS*NT;i+=256) sLf[i]=g_Lf[i];
    if (tid<NT){ sLc[tid]=g_Lc[tid]; sLb[tid]=g_Lb[tid]; sP[tid]=0.f; sC[tid]=0; }
    __syncthreads();
    int i = blockIdx.x*256+tid;
    int opv=op[i], av=a[i], bv=b[i]; float cv=(float)c[i];
    float l[NT]; float mx=-1e30f; int best=0;
    #pragma unroll
    for (int t=0;t<NT;t++){
        float v = sLf[opv*NT+t]+sLg[av*NT+t]+sLh[bv*NT+t]+cv*sLc[t]+sLb[t];
        l[t]=v;
        if (v>mx){mx=v;best=t;}
    }
    float den=0.f;
    #pragma unroll
    for (int t=0;t<NT;t++){ l[t]=__expf(l[t]-mx); den+=l[t]; }
    float inv = 1.f/den;
    #pragma unroll
    for (int t=0;t<NT;t++){
        float v = l[t]*inv;
        #pragma unroll
        for (int o=16;o;o>>=1) v += __shfl_xor_sync(0xffffffffu, v, o);
        if (lane==0) atomicAdd(&sP[t], v);
    }
    #pragma unroll
    for (int t=0;t<NT;t++){
        unsigned bal = __ballot_sync(0xffffffffu, best==t);
        if (lane==0 && bal) atomicAdd(&sC[t], (int)__popc(bal));
    }
    g_idx[i]=(unsigned char)best; g_gate[i]=inv; outIdx[i]=(float)best;
    __syncthreads();
    if (tid<NT){
        atomicAdd(&g_cnt[tid], sC[tid]);
        atomicAdd(&g_sumP[tid], (double)sP[tid]);
    }
}

// ---------------- k_part ----------------
__global__ void k_part(){
    __shared__ int po[NT], pc[NT];
    int tid=threadIdx.x;
    if (tid==0){
        int acc=0, nb=0;
        for (int t=0;t<NT;t++){
            po[t]=acc; g_po[t]=acc;
            int cnt = g_cnt[t]; pc[t]=cnt;
            int bl = (cnt+MROWS-1)/MROWS;
            for (int bidx=0;bidx<bl;bidx++){ g_bmT[nb]=t; g_bmR[nb]=acc+bidx*MROWS; nb++; }
            acc += bl*MROWS;
        }
        g_nblocks = nb;
    }
    __syncthreads();
    for (int t=0;t<NT;t++){
        int cnt=pc[t]; int pad = ((cnt+MROWS-1)/MROWS)*MROWS;
        for (int p=cnt+tid; p<pad; p+=256) g_src[po[t]+p] = -1;
    }
}

// ---------------- k_scat ----------------
__global__ void k_scat(){
    __shared__ int scnt[NT], sbase[NT];
    int tid=threadIdx.x;
    if (tid<NT) scnt[tid]=0;
    __syncthreads();
    int i = blockIdx.x*256+tid;
    int t = (int)g_idx[i];
    int rank = atomicAdd(&scnt[t],1);
    __syncthreads();
    if (tid<NT) sbase[tid]=atomicAdd(&g_fill[tid], scnt[tid]);
    __syncthreads();
    g_src[g_po[t]+sbase[t]+rank]=i;
}

// ---------------- k_ffn: fp16 m16n8k16 mma + ldmatrix ----------------
// smem: sX[128][SLDH] half, sW[128][SLDH] half, sG[128][SLDH] half
__global__ void __launch_bounds__(256,1) k_ffn(
    const int* __restrict__ op, const int* __restrict__ aIn,
    const int* __restrict__ bIn, const int* __restrict__ cIn,
    const float* __restrict__ Win, const float* __restrict__ bin,
    const float* __restrict__ Wh1, const float* __restrict__ bh1,
    const float* __restrict__ Wh2, const float* __restrict__ bh2,
    float* __restrict__ outR)
{
    extern __shared__ __half sm[];
    __half* sX = sm;
    __half* sW = sm + 128*SLDH;
    __half* sG = sm + 2*128*SLDH;
    __shared__ float sGate[MROWS];
    __shared__ int   sSrc[MROWS];
    __shared__ float sWh2[512], sbh1[64], sbh2[8];

    int bid = blockIdx.x;
    if (bid >= g_nblocks) return;
    int t  = g_bmT[bid], r0 = g_bmR[bid];
    int tid = threadIdx.x;
    int wid = tid>>5, lane = tid&31;
    int grp = lane>>2, tq = lane&3;
    int wm = wid&3, wn = wid>>2;            // 4 m-warps x 2 n-warps
    float s1 = g_s1[t], s2 = g_s2[t];

    uint32_t bX = smem_u32(sX), bW = smem_u32(sW), bG = smem_u32(sG);
    // ldmatrix source offsets (lane-dependent)
    uint32_t aoff = (uint32_t)((lane&15)*SLDH + (lane>>4)*8)*2;  // A: x4
    uint32_t boff = (uint32_t)((lane&7)*SLDH + ((lane>>3)&1)*8)*2; // B: x2

    // ---- build X tile (fp16); 2 threads/row ----
    {
        int row = tid>>1, half = tid&1;
        int token = g_src[r0+row];
        if (half==0){ sSrc[row]=token; sGate[row]=(token>=0)?g_gate[token]:0.f; }
        const float* wc = Win + 48*DM;
        __half* dst = sX + row*SLDH + half*64;
        if (token>=0){
            int opv=op[token], av=aIn[token], bv=bIn[token]; float cv=(float)cIn[token];
            const float* tf=&g_Tf[opv*DM+half*64]; const float* tg=&g_Tg[av*DM+half*64];
            const float* th=&g_Th[bv*DM+half*64];
            const float* wcc=wc+half*64; const float* bb=bin+half*64;
            #pragma unroll 8
            for (int d=0; d<64; d+=2){
                float x0 = tf[d]+tg[d]+th[d]+cv*wcc[d]+bb[d];
                float x1 = tf[d+1]+tg[d+1]+th[d+1]+cv*wcc[d+1]+bb[d+1];
                *(__half2*)(dst+d) = h2pack(x0,x1);
            }
        } else {
            #pragma unroll 8
            for (int d=0; d<64; d+=2) *(uint32_t*)(dst+d) = 0u;
        }
    }
    for (int i=tid;i<512;i+=256) sWh2[i]=Wh2[i];
    if (tid<64) sbh1[tid]=bh1[tid];
    if (tid<8)  sbh2[tid]=bh2[tid];

    float c2[2][8][4];
    #pragma unroll
    for(int mt=0;mt<2;mt++)
        #pragma unroll
        for(int nt=0;nt<8;nt++)
            #pragma unroll
            for(int e=0;e<4;e++) c2[mt][nt][e]=0.f;

    const signed char* W1p = g_W1q + t*DFF*DM;
    const signed char* W2p = g_W2q + t*DM*DFF;

    for (int ch=0; ch<4; ch++){
        __syncthreads();
        // ---- W1 chunk [128 n][128 k] int8 -> sW fp16 ----
        {
            const char4* src = (const char4*)(W1p + ch*16384);
            #pragma unroll
            for (int rr=0;rr<16;rr++){
                int i = tid + rr*256;
                char4 v = src[i];
                int n = i>>5, k4 = (i&31)*4;
                __half* dst = sW + n*SLDH + k4;
                *(__half2*)(dst)   = h2pack((float)v.x,(float)v.y);
                *(__half2*)(dst+2) = h2pack((float)v.z,(float)v.w);
            }
        }
        __syncthreads();
        float c1[2][8][4];
        #pragma unroll
        for(int mt=0;mt<2;mt++)
            #pragma unroll
            for(int nt=0;nt<8;nt++)
                #pragma unroll
                for(int e=0;e<4;e++) c1[mt][nt][e]=0.f;
        #pragma unroll
        for (int kk=0;kk<8;kk++){
            uint32_t af[2][4];
            ldsm4(af[0], bX + aoff + (uint32_t)((wm*32)*SLDH + kk*16)*2);
            ldsm4(af[1], bX + aoff + (uint32_t)((wm*32+16)*SLDH + kk*16)*2);
            #pragma unroll
            for (int nt=0;nt<8;nt++){
                uint32_t bf[2];
                ldsm2(bf, bW + boff + (uint32_t)((wn*64+nt*8)*SLDH + kk*16)*2);
                mma16(c1[0][nt], af[0], bf);
                mma16(c1[1][nt], af[1], bf);
            }
        }
        __syncthreads();
        // ---- gelu epilogue -> sG fp16 ----
        #pragma unroll
        for (int mt=0;mt<2;mt++){
            int row0 = wm*32+mt*16+grp;
            #pragma unroll
            for (int nt=0;nt<8;nt++){
                int col = wn*64+nt*8+2*tq;
                float v0=s1*c1[mt][nt][0], v1=s1*c1[mt][nt][1];
                float v2=s1*c1[mt][nt][2], v3=s1*c1[mt][nt][3];
                float g0 = 0.5f*v0*(1.f+tanh_fast(0.7978845608f*(v0+0.044715f*v0*v0*v0)));
                float g1 = 0.5f*v1*(1.f+tanh_fast(0.7978845608f*(v1+0.044715f*v1*v1*v1)));
                float g2 = 0.5f*v2*(1.f+tanh_fast(0.7978845608f*(v2+0.044715f*v2*v2*v2)));
                float g3 = 0.5f*v3*(1.f+tanh_fast(0.7978845608f*(v3+0.044715f*v3*v3*v3)));
                *(__half2*)(sG + row0*SLDH + col)     = h2pack(g0,g1);
                *(__half2*)(sG + (row0+8)*SLDH + col) = h2pack(g2,g3);
            }
        }
        // ---- W2 chunk -> sW ----
        {
            #pragma unroll
            for (int rr=0;rr<16;rr++){
                int i = tid + rr*256;
                int n = i>>5, k4 = (i&31)*4;
                char4 v = *(const char4*)(W2p + n*DFF + ch*128 + k4);
                __half* dst = sW + n*SLDH + k4;
                *(__half2*)(dst)   = h2pack((float)v.x,(float)v.y);
                *(__half2*)(dst+2) = h2pack((float)v.z,(float)v.w);
            }
        }
        __syncthreads();
        // ---- GEMM2 accumulate ----
        #pragma unroll
        for (int kk=0;kk<8;kk++){
            uint32_t af[2][4];
            ldsm4(af[0], bG + aoff + (uint32_t)((wm*32)*SLDH + kk*16)*2);
            ldsm4(af[1], bG + aoff + (uint32_t)((wm*32+16)*SLDH + kk*16)*2);
            #pragma unroll
            for (int nt=0;nt<8;nt++){
                uint32_t bf[2];
                ldsm2(bf, bW + boff + (uint32_t)((wn*64+nt*8)*SLDH + kk*16)*2);
                mma16(c2[0][nt], af[0], bf);
                mma16(c2[1][nt], af[1], bf);
            }
        }
    }
    __syncthreads();
    // ---- gated output -> sX (head A, fp16) ----
    #pragma unroll
    for (int mt=0;mt<2;mt++){
        int row0 = wm*32+mt*16+grp;
        float ga = sGate[row0], gb = sGate[row0+8];
        #pragma unroll
        for (int nt=0;nt<8;nt++){
            int col = wn*64+nt*8+2*tq;
            *(__half2*)(sX + row0*SLDH + col)     = h2pack(s2*c2[mt][nt][0]*ga, s2*c2[mt][nt][1]*ga);
            *(__half2*)(sX + (row0+8)*SLDH + col) = h2pack(s2*c2[mt][nt][2]*gb, s2*c2[mt][nt][3]*gb);
        }
    }
    // ---- Wh1^T -> sW [64 n][128 k] ----
    for (int i=tid; i<64*64; i+=256){
        int n = i>>6, k = (i&63)*2;
        *(__half2*)(sW + n*SLDH + k) = h2pack(Wh1[k*64+n], Wh1[(k+1)*64+n]);
    }
    __syncthreads();
    // ---- head GEMM: [128x128] @ [64x128]^T ----
    float c3[2][4][4];
    #pragma unroll
    for(int mt=0;mt<2;mt++)
        #pragma unroll
        for(int nt=0;nt<4;nt++)
            #pragma unroll
            for(int e=0;e<4;e++) c3[mt][nt][e]=0.f;
    #pragma unroll
    for (int kk=0;kk<8;kk++){
        uint32_t af[2][4];
        ldsm4(af[0], bX + aoff + (uint32_t)((wm*32)*SLDH + kk*16)*2);
        ldsm4(af[1], bX + aoff + (uint32_t)((wm*32+16)*SLDH + kk*16)*2);
        #pragma unroll
        for (int nt=0;nt<4;nt++){
            uint32_t bf[2];
            ldsm2(bf, bW + boff + (uint32_t)((wn*32+nt*8)*SLDH + kk*16)*2);
            mma16(c3[0][nt], af[0], bf);
            mma16(c3[1][nt], af[1], bf);
        }
    }
    __syncthreads();
    // ---- h = relu(c3+bh1) -> float buffer (reuse sX) ----
    float* sH = (float*)sX;   // [128][66]
    #pragma unroll
    for (int mt=0;mt<2;mt++){
        int row0 = wm*32+mt*16+grp;
        #pragma unroll
        for (int nt=0;nt<4;nt++){
            int col = wn*32+nt*8+2*tq;
            sH[row0*66+col]       = fmaxf(c3[mt][nt][0]+sbh1[col],   0.f);
            sH[row0*66+col+1]     = fmaxf(c3[mt][nt][1]+sbh1[col+1], 0.f);
            sH[(row0+8)*66+col]   = fmaxf(c3[mt][nt][2]+sbh1[col],   0.f);
            sH[(row0+8)*66+col+1] = fmaxf(c3[mt][nt][3]+sbh1[col+1], 0.f);
        }
    }
    __syncthreads();
    // ---- final 64->8 + sigmoid (2 threads/row) ----
    {
        int row = tid>>1, c0 = (tid&1)*4;
        int token = sSrc[row];
        if (token>=0){
            float acc0=sbh2[c0], acc1=sbh2[c0+1], acc2=sbh2[c0+2], acc3=sbh2[c0+3];
            #pragma unroll 8
            for (int k2=0;k2<64;k2++){
                float hv = sH[row*66+k2];
                acc0 += hv*sWh2[k2*8+c0];
                acc1 += hv*sWh2[k2*8+c0+1];
                acc2 += hv*sWh2[k2*8+c0+2];
                acc3 += hv*sWh2[k2*8+c0+3];
            }
            float* o = outR + (size_t)token*8 + c0;
            o[0] = 1.f/(1.f+__expf(-acc0));
            o[1] = 1.f/(1.f+__expf(-acc1));
            o[2] = 1.f/(1.f+__expf(-acc2));
            o[3] = 1.f/(1.f+__expf(-acc3));
        }
    }
}

// ---------------- k_aux ----------------
__global__ void k_aux(float* __restrict__ aux){
    if (threadIdx.x==0){
        double sp=0.0, cp[4]={0,0,0,0};
        for (int t=0;t<NT;t++){
            double frac = (double)g_cnt[t]/(double)BTOK;
            double mp = g_sumP[t]/(double)BTOK;
            sp += frac*mp;
            cp[t>>2] += mp;
        }
        double sparsity = 16.0*sp;
        double tern = g_res[0]/1048576.0 + g_res[1]/1048576.0;
        double divv = 0.0;
        for (int i=0;i<4;i++) divv += cp[i]*log(cp[i]+1e-9);
        aux[0] = (float)(0.01*tern + 0.005*sparsity + 0.01*divv);
    }
}

// ---------------- launch ----------------
extern "C" void kernel_launch(void* const* d_in, const int* in_sizes, int n_in,
                              void* d_out, int out_size){
    const int *op=nullptr,*a=nullptr,*b=nullptr,*c=nullptr;
    const float *oe=nullptr,*Win=nullptr,*bin=nullptr,*Wr=nullptr,*W1=nullptr,*W2=nullptr;
    const float *Wh1=nullptr,*bh1=nullptr,*Wh2=nullptr,*bh2=nullptr;
    int nb_=0, nw=0;
    for (int i=0;i<n_in;i++){
        int s = in_sizes[i]; void* p = (void*)d_in[i];
        switch(s){
            case BTOK:
                if(nb_==0) op=(const int*)p; else if(nb_==1) a=(const int*)p;
                else if(nb_==2) b=(const int*)p; else c=(const int*)p;
                nb_++; break;
            case 256:  oe=(const float*)p; break;
            case 6272: Win=(const float*)p; break;
            case 128:  bin=(const float*)p; break;
            case 2048: Wr=(const float*)p; break;
            case 1048576: if(nw==0) W1=(const float*)p; else W2=(const float*)p; nw++; break;
            case 8192: Wh1=(const float*)p; break;
            case 64:   bh1=(const float*)p; break;
            case 512:  Wh2=(const float*)p; break;
            case 8:    bh2=(const float*)p; break;
            default: break;
        }
    }
    float* out = (float*)d_out;
    int smem = 3*128*SLDH*2;
    cudaFuncSetAttribute(k_ffn, cudaFuncAttributeMaxDynamicSharedMemorySize, smem);

    k_init<<<1,32>>>();
    k_tables<<<260,256>>>(oe,Win);
    k_lt<<<33,256>>>(Wr,Win,bin);
    k_scalep<<<512,256>>>(W1,W2);
    k_sfin<<<1,32>>>();
    k_quant<<<8192,256>>>(W1,W2);
    k_route<<<BTOK/256,256>>>(op,a,b,c,out + (size_t)BTOK*8);
    k_part<<<1,256>>>();
    k_scat<<<BTOK/256,256>>>();
    k_ffn<<<MAXBLK,256,smem>>>(op,a,b,c,Win,bin,Wh1,bh1,Wh2,bh2,out);
    k_aux<<<1,32>>>(out + (size_t)BTOK*9);
}

// round 6
// speedup vs baseline: 1.5393x; 1.0544x over previous
#include <cuda_runtime.h>
#include <cuda_fp16.h>
#include <cstdint>

#define BTOK 262144
#define DM 128
#define DFF 512
#define NT 16
#define NOPS 8
#define EMB 32
#define MROWS 128
#define SLDH 136
#define MAXBLK (BTOK/MROWS + NT)
#define TSTR (BTOK + 128)

// ---------------- device scratch ----------------
__device__ float g_Tf[NOPS*DM];
__device__ float g_Tg[256*DM];
__device__ float g_Th[256*DM];
__device__ float g_Lf[NOPS*NT];
__device__ float g_Lg[256*NT];
__device__ float g_Lh[256*NT];
__device__ float g_Lc[NT];
__device__ float g_Lb[NT];
__device__ float g_s1[NT], g_s2[NT];
__device__ double g_sabs[32];
__device__ double g_res[2];
__device__ __half g_W1h[NT*DFF*DM];   // [t][n(dff)][k(d)]
__device__ __half g_W2h[NT*DM*DFF];   // [t][n(d)][k(dff)]
__device__ double g_sumP[NT];
__device__ int g_fill[NT];
__device__ int g_nblocks;
__device__ float g_gate[BTOK];
__device__ int g_src[NT*TSTR];
__device__ int g_bmT[MAXBLK];
__device__ int g_bmR[MAXBLK];

// ---------------- helpers ----------------
__device__ __forceinline__ float tanh_fast(float v){
    float r; asm("tanh.approx.f32 %0, %1;" : "=f"(r) : "f"(v)); return r;
}
__device__ __forceinline__ uint32_t smem_u32(const void* p){
    uint32_t a;
    asm("{ .reg .u64 t; cvta.to.shared.u64 t, %1; cvt.u32.u64 %0, t; }":"=r"(a):"l"(p));
    return a;
}
__device__ __forceinline__ void ldsm4(uint32_t* r, uint32_t addr){
    asm volatile("ldmatrix.sync.aligned.m8n8.x4.shared.b16 {%0,%1,%2,%3}, [%4];"
        : "=r"(r[0]),"=r"(r[1]),"=r"(r[2]),"=r"(r[3]) : "r"(addr));
}
__device__ __forceinline__ void ldsm2(uint32_t* r, uint32_t addr){
    asm volatile("ldmatrix.sync.aligned.m8n8.x2.shared.b16 {%0,%1}, [%2];"
        : "=r"(r[0]),"=r"(r[1]) : "r"(addr));
}
__device__ __forceinline__ void mma16(float* c, const uint32_t* a, const uint32_t* b){
    asm volatile("mma.sync.aligned.m16n8k16.row.col.f32.f16.f16.f32 "
        "{%0,%1,%2,%3},{%4,%5,%6,%7},{%8,%9},{%0,%1,%2,%3};"
        : "+f"(c[0]),"+f"(c[1]),"+f"(c[2]),"+f"(c[3])
        : "r"(a[0]),"r"(a[1]),"r"(a[2]),"r"(a[3]),"r"(b[0]),"r"(b[1]));
}
__device__ __forceinline__ __half2 h2pack(float a, float b){
    return __floats2half2_rn(a, b);
}
__device__ __forceinline__ void cpa16(uint32_t dst, const void* src){
    asm volatile("cp.async.cg.shared.global [%0], [%1], 16;" :: "r"(dst),"l"(src):"memory");
}
__device__ __forceinline__ void cpa_commit(){
    asm volatile("cp.async.commit_group;":::"memory");
}
__device__ __forceinline__ void cpa_wait0(){
    asm volatile("cp.async.wait_group 0;":::"memory");
}

// ---------------- k_init ----------------
__global__ void k_init(){
    int i = threadIdx.x;
    if (i < NT){ g_sumP[i]=0.0; g_fill[i]=0; }
    if (i < 32) g_sabs[i]=0.0;
    if (i < 2)  g_res[i]=0.0;
}

// ---------------- k_tables ----------------
__global__ void k_tables(const float* __restrict__ oe, const float* __restrict__ Win){
    int gid = blockIdx.x*256 + threadIdx.x;
    if (gid < 32768){
        int av = gid >> 7, d = gid & 127;
        float s = 0.f;
        #pragma unroll
        for (int i=0;i<8;i++) if ((av>>i)&1) s += Win[(32+i)*DM + d];
        g_Tg[av*DM+d] = s;
    } else if (gid < 65536){
        int g2 = gid - 32768;
        int bv = g2 >> 7, d = g2 & 127;
        float s = 0.f;
        #pragma unroll
        for (int i=0;i<8;i++) if ((bv>>i)&1) s += Win[(40+i)*DM + d];
        g_Th[bv*DM+d] = s;
    } else if (gid < 66560){
        int g2 = gid - 65536;
        int op = g2 >> 7, d = g2 & 127;
        float s = 0.f;
        #pragma unroll
        for (int j=0;j<EMB;j++) s += oe[op*EMB+j]*Win[j*DM+d];
        g_Tf[op*DM+d] = s;
    }
}

// ---------------- k_lt ----------------
__global__ void k_lt(const float* __restrict__ Wr, const float* __restrict__ Win,
                     const float* __restrict__ bin){
    int gid = blockIdx.x*256+threadIdx.x;
    if (gid < 4096){
        int av=gid>>4, t=gid&15; float s=0.f;
        for(int d=0;d<DM;d++) s += g_Tg[av*DM+d]*Wr[d*NT+t];
        g_Lg[gid]=s;
    } else if (gid < 8192){
        int g2=gid-4096; int bv=g2>>4,t=g2&15; float s=0.f;
        for(int d=0;d<DM;d++) s += g_Th[bv*DM+d]*Wr[d*NT+t];
        g_Lh[g2]=s;
    } else if (gid < 8320){
        int g2=gid-8192; int op=g2>>4,t=g2&15; float s=0.f;
        for(int d=0;d<DM;d++) s += g_Tf[op*DM+d]*Wr[d*NT+t];
        g_Lf[g2]=s;
    } else if (gid < 8336){
        int t=gid-8320; float s=0.f;
        for(int d=0;d<DM;d++) s += Win[48*DM+d]*Wr[d*NT+t];
        g_Lc[t]=s;
    } else if (gid < 8352){
        int t=gid-8336; float s=0.f;
        for(int d=0;d<DM;d++) s += bin[d]*Wr[d*NT+t];
        g_Lb[t]=s;
    }
}

// ---------------- k_scalep ----------------
__global__ void k_scalep(const float* __restrict__ W1, const float* __restrict__ W2){
    __shared__ double red[256];
    int tile = blockIdx.x >> 4;
    int sub  = blockIdx.x & 15;
    const float* W = (tile < 16 ? W1 + tile*65536 : W2 + (tile-16)*65536) + sub*4096;
    const float4* W4 = (const float4*)W;
    double s = 0.0;
    #pragma unroll
    for (int r=0;r<4;r++){
        float4 v = W4[threadIdx.x + r*256];
        s += (double)(fabsf(v.x)+fabsf(v.y)+fabsf(v.z)+fabsf(v.w));
    }
    red[threadIdx.x]=s; __syncthreads();
    for (int o=128;o;o>>=1){ if(threadIdx.x<o) red[threadIdx.x]+=red[threadIdx.x+o]; __syncthreads(); }
    if (!threadIdx.x) atomicAdd(&g_sabs[tile], red[0]);
}

// ---------------- k_sfin ----------------
__global__ void k_sfin(){
    int t = threadIdx.x;
    if (t < 16) g_s1[t] = (float)(g_sabs[t]/65536.0);
    else if (t < 32) g_s2[t-16] = (float)(g_sabs[t]/65536.0);
}

// ---------------- k_quant: ternary signs as fp16 (transposed) + residual ----------------
__global__ void k_quant(const float* __restrict__ W1, const float* __restrict__ W2){
    __shared__ double red[256];
    int gid = blockIdx.x*256+threadIdx.x;
    int m = gid >> 20;
    int e = gid & 0xFFFFF;
    int t = e >> 16, j = e & 0xFFFF;
    float w, s; int outi;
    if (!m){ w = W1[e]; s = g_s1[t]; int k=j>>9, n=j&511; outi = t*65536 + n*128 + k; }
    else   { w = W2[e]; s = g_s2[t]; int kk=j>>7, nn=j&127; outi = t*65536 + nn*512 + kk; }
    float aw = fabsf(w);
    bool nz = aw > 0.7f*s;
    float q = nz ? (w>0.f?1.f:-1.f) : 0.f;
    float r = nz ? fabsf(aw - s) : aw;
    if (!m) g_W1h[outi]=__float2half(q); else g_W2h[outi]=__float2half(q);
    red[threadIdx.x]=(double)r; __syncthreads();
    for(int o=128;o;o>>=1){ if(threadIdx.x<o) red[threadIdx.x]+=red[threadIdx.x+o]; __syncthreads(); }
    if (!threadIdx.x) atomicAdd(&g_res[m], red[0]);
}

// ---------------- k_route: logits, softmax, argmax, stats, fused scatter ----------------
__global__ void k_route(const int* __restrict__ op, const int* __restrict__ a,
                        const int* __restrict__ b, const int* __restrict__ c,
                        float* __restrict__ outIdx){
    __shared__ float sLf[NOPS*NT], sLg[256*NT], sLh[256*NT], sLc[NT], sLb[NT];
    __shared__ float sP[NT]; __shared__ int sC[NT]; __shared__ int sBase[NT];
    int tid = threadIdx.x;
    int lane = tid & 31;
    for (int i=tid;i<256*NT;i+=256){ sLg[i]=g_Lg[i]; sLh[i]=g_Lh[i]; }
    for (int i=tid;i<NOPS*NT;i+=256) sLf[i]=g_Lf[i];
    if (tid<NT){ sLc[tid]=g_Lc[tid]; sLb[tid]=g_Lb[tid]; sP[tid]=0.f; sC[tid]=0; }
    __syncthreads();
    int i = blockIdx.x*256+tid;
    int opv=op[i], av=a[i], bv=b[i]; float cv=(float)c[i];
    float l[NT]; float mx=-1e30f; int best=0;
    #pragma unroll
    for (int t=0;t<NT;t++){
        float v = sLf[opv*NT+t]+sLg[av*NT+t]+sLh[bv*NT+t]+cv*sLc[t]+sLb[t];
        l[t]=v;
        if (v>mx){mx=v;best=t;}
    }
    float den=0.f;
    #pragma unroll
    for (int t=0;t<NT;t++){ l[t]=__expf(l[t]-mx); den+=l[t]; }
    float inv = 1.f/den;
    #pragma unroll
    for (int t=0;t<NT;t++){
        float v = l[t]*inv;
        #pragma unroll
        for (int o=16;o;o>>=1) v += __shfl_xor_sync(0xffffffffu, v, o);
        if (lane==0) atomicAdd(&sP[t], v);
    }
    int rank = atomicAdd(&sC[best], 1);
    g_gate[i]=inv; outIdx[i]=(float)best;
    __syncthreads();
    if (tid<NT){
        sBase[tid] = atomicAdd(&g_fill[tid], sC[tid]);
        atomicAdd(&g_sumP[tid], (double)sP[tid]);
    }
    __syncthreads();
    g_src[best*TSTR + sBase[best] + rank] = i;
}

// ---------------- k_part ----------------
__global__ void k_part(){
    __shared__ int pc[NT];
    int tid=threadIdx.x;
    if (tid==0){
        int nb=0;
        for (int t=0;t<NT;t++){
            int cnt = g_fill[t]; pc[t]=cnt;
            int bl = (cnt+MROWS-1)/MROWS;
            for (int bidx=0;bidx<bl;bidx++){ g_bmT[nb]=t; g_bmR[nb]=t*TSTR + bidx*MROWS; nb++; }
        }
        g_nblocks = nb;
    }
    __syncthreads();
    for (int t=0;t<NT;t++){
        int cnt=pc[t]; int pad = ((cnt+MROWS-1)/MROWS)*MROWS;
        for (int p=cnt+tid; p<pad; p+=256) g_src[t*TSTR+p] = -1;
    }
}

// ---------------- k_ffn: fp16 mma + ldmatrix + cp.async double-buffered weights ----------------
__global__ void __launch_bounds__(256,1) k_ffn(
    const int* __restrict__ op, const int* __restrict__ aIn,
    const int* __restrict__ bIn, const int* __restrict__ cIn,
    const float* __restrict__ Win, const float* __restrict__ bin,
    const float* __restrict__ Wh1, const float* __restrict__ bh1,
    const float* __restrict__ Wh2, const float* __restrict__ bh2,
    float* __restrict__ outR)
{
    extern __shared__ __half sm[];
    __half* sX  = sm;
    __half* sW0 = sm + 128*SLDH;
    __half* sW1 = sm + 2*128*SLDH;
    __half* sG  = sm + 3*128*SLDH;
    __shared__ float sGate[MROWS];
    __shared__ int   sSrc[MROWS];
    __shared__ float sWh2[512], sbh1[64], sbh2[8];

    int bid = blockIdx.x;
    if (bid >= g_nblocks) return;
    int t  = g_bmT[bid], r0 = g_bmR[bid];
    int tid = threadIdx.x;
    int wid = tid>>5, lane = tid&31;
    int grp = lane>>2, tq = lane&3;
    int wm = wid&3, wn = wid>>2;            // 4 m-warps x 2 n-warps
    float s1 = g_s1[t], s2 = g_s2[t];

    uint32_t bX = smem_u32(sX), bG = smem_u32(sG);
    uint32_t bufs[2] = { smem_u32(sW0), smem_u32(sW1) };
    uint32_t aoff  = (uint32_t)((lane&15)*SLDH + (lane>>4)*8)*2;
    uint32_t boff4 = (uint32_t)(((lane&7) + ((lane>>4)<<3))*SLDH + ((lane>>3)&1)*8)*2;

    const __half* W1p = g_W1h + t*65536;
    const __half* W2p = g_W2h + t*65536;

    // ---- prefetch stage 0 (W1 chunk 0) into buf0 ----
    {
        const __half* src = W1p;
        #pragma unroll
        for (int j=0;j<8;j++){
            int i = tid + j*256;
            int row = i>>4, ck = i&15;
            cpa16(bufs[0] + (uint32_t)(row*SLDH + ck*8)*2, src + row*128 + ck*8);
        }
        cpa_commit();
    }

    // ---- build X tile (fp16); 2 threads/row ----
    {
        int row = tid>>1, half = tid&1;
        int token = g_src[r0+row];
        if (half==0){ sSrc[row]=token; sGate[row]=(token>=0)?g_gate[token]:0.f; }
        const float* wc = Win + 48*DM;
        __half* dst = sX + row*SLDH + half*64;
        if (token>=0){
            int opv=op[token], av=aIn[token], bv=bIn[token]; float cv=(float)cIn[token];
            const float* tf=&g_Tf[opv*DM+half*64]; const float* tg=&g_Tg[av*DM+half*64];
            const float* th=&g_Th[bv*DM+half*64];
            const float* wcc=wc+half*64; const float* bb=bin+half*64;
            #pragma unroll 8
            for (int d=0; d<64; d+=2){
                float x0 = tf[d]+tg[d]+th[d]+cv*wcc[d]+bb[d];
                float x1 = tf[d+1]+tg[d+1]+th[d+1]+cv*wcc[d+1]+bb[d+1];
                *(__half2*)(dst+d) = h2pack(x0,x1);
            }
        } else {
            #pragma unroll 8
            for (int d=0; d<64; d+=2) *(uint32_t*)(dst+d) = 0u;
        }
    }
    for (int i=tid;i<512;i+=256) sWh2[i]=Wh2[i];
    if (tid<64) sbh1[tid]=bh1[tid];
    if (tid<8)  sbh2[tid]=bh2[tid];

    float c2[2][8][4];
    #pragma unroll
    for(int mt=0;mt<2;mt++)
        #pragma unroll
        for(int nt=0;nt<8;nt++)
            #pragma unroll
            for(int e=0;e<4;e++) c2[mt][nt][e]=0.f;

    cpa_wait0();
    __syncthreads();

    for (int s=0;s<8;s++){
        // prefetch next tile into alternate buffer
        if (s<7){
            int sn = s+1, ch = sn>>1;
            uint32_t dstb = bufs[sn&1];
            if (!(sn&1)){
                const __half* src = W1p + ch*16384;
                #pragma unroll
                for (int j=0;j<8;j++){
                    int i = tid + j*256;
                    int row = i>>4, ck = i&15;
                    cpa16(dstb + (uint32_t)(row*SLDH + ck*8)*2, src + row*128 + ck*8);
                }
            } else {
                const __half* src = W2p + ch*128;
                #pragma unroll
                for (int j=0;j<8;j++){
                    int i = tid + j*256;
                    int row = i>>4, ck = i&15;
                    cpa16(dstb + (uint32_t)(row*SLDH + ck*8)*2, src + row*512 + ck*8);
                }
            }
            cpa_commit();
        }
        uint32_t bw = bufs[s&1];
        if (!(s&1)){
            // GEMM1: X @ W1[ch] -> c1; gelu -> sG
            float c1[2][8][4];
            #pragma unroll
            for(int mt=0;mt<2;mt++)
                #pragma unroll
                for(int nt=0;nt<8;nt++)
                    #pragma unroll
                    for(int e=0;e<4;e++) c1[mt][nt][e]=0.f;
            #pragma unroll
            for (int kk=0;kk<8;kk++){
                uint32_t af[2][4];
                ldsm4(af[0], bX + aoff + (uint32_t)((wm*32)*SLDH + kk*16)*2);
                ldsm4(af[1], bX + aoff + (uint32_t)((wm*32+16)*SLDH + kk*16)*2);
                #pragma unroll
                for (int ntp=0;ntp<4;ntp++){
                    uint32_t bq[4];
                    ldsm4(bq, bw + boff4 + (uint32_t)((wn*64+ntp*16)*SLDH + kk*16)*2);
                    mma16(c1[0][2*ntp],   af[0], bq);
                    mma16(c1[1][2*ntp],   af[1], bq);
                    mma16(c1[0][2*ntp+1], af[0], bq+2);
                    mma16(c1[1][2*ntp+1], af[1], bq+2);
                }
            }
            #pragma unroll
            for (int mt=0;mt<2;mt++){
                int row0 = wm*32+mt*16+grp;
                #pragma unroll
                for (int nt=0;nt<8;nt++){
                    int col = wn*64+nt*8+2*tq;
                    float v0=s1*c1[mt][nt][0], v1=s1*c1[mt][nt][1];
                    float v2=s1*c1[mt][nt][2], v3=s1*c1[mt][nt][3];
                    float g0 = 0.5f*v0*(1.f+tanh_fast(0.7978845608f*(v0+0.044715f*v0*v0*v0)));
                    float g1 = 0.5f*v1*(1.f+tanh_fast(0.7978845608f*(v1+0.044715f*v1*v1*v1)));
                    float g2 = 0.5f*v2*(1.f+tanh_fast(0.7978845608f*(v2+0.044715f*v2*v2*v2)));
                    float g3 = 0.5f*v3*(1.f+tanh_fast(0.7978845608f*(v3+0.044715f*v3*v3*v3)));
                    *(__half2*)(sG + row0*SLDH + col)     = h2pack(g0,g1);
                    *(__half2*)(sG + (row0+8)*SLDH + col) = h2pack(g2,g3);
                }
            }
        } else {
            // GEMM2: sG @ W2[ch] accumulate into c2
            #pragma unroll
            for (int kk=0;kk<8;kk++){
                uint32_t af[2][4];
                ldsm4(af[0], bG + aoff + (uint32_t)((wm*32)*SLDH + kk*16)*2);
                ldsm4(af[1], bG + aoff + (uint32_t)((wm*32+16)*SLDH + kk*16)*2);
                #pragma unroll
                for (int ntp=0;ntp<4;ntp++){
                    uint32_t bq[4];
                    ldsm4(bq, bw + boff4 + (uint32_t)((wn*64+ntp*16)*SLDH + kk*16)*2);
                    mma16(c2[0][2*ntp],   af[0], bq);
                    mma16(c2[1][2*ntp],   af[1], bq);
                    mma16(c2[0][2*ntp+1], af[0], bq+2);
                    mma16(c2[1][2*ntp+1], af[1], bq+2);
                }
            }
        }
        cpa_wait0();
        __syncthreads();
    }

    // ---- gated output -> sX (head A, fp16) ----
    #pragma unroll
    for (int mt=0;mt<2;mt++){
        int row0 = wm*32+mt*16+grp;
        float ga = sGate[row0], gb = sGate[row0+8];
        #pragma unroll
        for (int nt=0;nt<8;nt++){
            int col = wn*64+nt*8+2*tq;
            *(__half2*)(sX + row0*SLDH + col)     = h2pack(s2*c2[mt][nt][0]*ga, s2*c2[mt][nt][1]*ga);
            *(__half2*)(sX + (row0+8)*SLDH + col) = h2pack(s2*c2[mt][nt][2]*gb, s2*c2[mt][nt][3]*gb);
        }
    }
    // ---- Wh1^T -> sW0 [64 n][128 k] ----
    for (int i=tid; i<64*64; i+=256){
        int n = i>>6, k = (i&63)*2;
        *(__half2*)(sW0 + n*SLDH + k) = h2pack(Wh1[k*64+n], Wh1[(k+1)*64+n]);
    }
    __syncthreads();
    // ---- head GEMM: [128x128] @ [64x128]^T ----
    uint32_t bw0 = bufs[0];
    float c3[2][4][4];
    #pragma unroll
    for(int mt=0;mt<2;mt++)
        #pragma unroll
        for(int nt=0;nt<4;nt++)
            #pragma unroll
            for(int e=0;e<4;e++) c3[mt][nt][e]=0.f;
    #pragma unroll
    for (int kk=0;kk<8;kk++){
        uint32_t af[2][4];
        ldsm4(af[0], bX + aoff + (uint32_t)((wm*32)*SLDH + kk*16)*2);
        ldsm4(af[1], bX + aoff + (uint32_t)((wm*32+16)*SLDH + kk*16)*2);
        #pragma unroll
        for (int ntp=0;ntp<2;ntp++){
            uint32_t bq[4];
            ldsm4(bq, bw0 + boff4 + (uint32_t)((wn*32+ntp*16)*SLDH + kk*16)*2);
            mma16(c3[0][2*ntp],   af[0], bq);
            mma16(c3[1][2*ntp],   af[1], bq);
            mma16(c3[0][2*ntp+1], af[0], bq+2);
            mma16(c3[1][2*ntp+1], af[1], bq+2);
        }
    }
    __syncthreads();
    // ---- h = relu(c3+bh1) -> float buffer (reuse sX) ----
    float* sH = (float*)sX;   // [128][66]
    #pragma unroll
    for (int mt=0;mt<2;mt++){
        int row0 = wm*32+mt*16+grp;
        #pragma unroll
        for (int nt=0;nt<4;nt++){
            int col = wn*32+nt*8+2*tq;
            sH[row0*66+col]       = fmaxf(c3[mt][nt][0]+sbh1[col],   0.f);
            sH[row0*66+col+1]     = fmaxf(c3[mt][nt][1]+sbh1[col+1], 0.f);
            sH[(row0+8)*66+col]   = fmaxf(c3[mt][nt][2]+sbh1[col],   0.f);
            sH[(row0+8)*66+col+1] = fmaxf(c3[mt][nt][3]+sbh1[col+1], 0.f);
        }
    }
    __syncthreads();
    // ---- final 64->8 + sigmoid (2 threads/row) ----
    {
        int row = tid>>1, c0 = (tid&1)*4;
        int token = sSrc[row];
        if (token>=0){
            float acc0=sbh2[c0], acc1=sbh2[c0+1], acc2=sbh2[c0+2], acc3=sbh2[c0+3];
            #pragma unroll 8
            for (int k2=0;k2<64;k2++){
                float hv = sH[row*66+k2];
                acc0 += hv*sWh2[k2*8+c0];
                acc1 += hv*sWh2[k2*8+c0+1];
                acc2 += hv*sWh2[k2*8+c0+2];
                acc3 += hv*sWh2[k2*8+c0+3];
            }
            float* o = outR + (size_t)token*8 + c0;
            o[0] = 1.f/(1.f+__expf(-acc0));
            o[1] = 1.f/(1.f+__expf(-acc1));
            o[2] = 1.f/(1.f+__expf(-acc2));
            o[3] = 1.f/(1.f+__expf(-acc3));
        }
    }
}

// ---------------- k_aux ----------------
__global__ void k_aux(float* __restrict__ aux){
    if (threadIdx.x==0){
        double sp=0.0, cp[4]={0,0,0,0};
        for (int t=0;t<NT;t++){
            double frac = (double)g_fill[t]/(double)BTOK;
            double mp = g_sumP[t]/(double)BTOK;
            sp += frac*mp;
            cp[t>>2] += mp;
        }
        double sparsity = 16.0*sp;
        double tern = g_res[0]/1048576.0 + g_res[1]/1048576.0;
        double divv = 0.0;
        for (int i=0;i<4;i++) divv += cp[i]*log(cp[i]+1e-9);
        aux[0] = (float)(0.01*tern + 0.005*sparsity + 0.01*divv);
    }
}

// ---------------- launch ----------------
extern "C" void kernel_launch(void* const* d_in, const int* in_sizes, int n_in,
                              void* d_out, int out_size){
    const int *op=nullptr,*a=nullptr,*b=nullptr,*c=nullptr;
    const float *oe=nullptr,*Win=nullptr,*bin=nullptr,*Wr=nullptr,*W1=nullptr,*W2=nullptr;
    const float *Wh1=nullptr,*bh1=nullptr,*Wh2=nullptr,*bh2=nullptr;
    int nb_=0, nw=0;
    for (int i=0;i<n_in;i++){
        int s = in_sizes[i]; void* p = (void*)d_in[i];
        switch(s){
            case BTOK:
                if(nb_==0) op=(const int*)p; else if(nb_==1) a=(const int*)p;
                else if(nb_==2) b=(const int*)p; else c=(const int*)p;
                nb_++; break;
            case 256:  oe=(const float*)p; break;
            case 6272: Win=(const float*)p; break;
            case 128:  bin=(const float*)p; break;
            case 2048: Wr=(const float*)p; break;
            case 1048576: if(nw==0) W1=(const float*)p; else W2=(const float*)p; nw++; break;
            case 8192: Wh1=(const float*)p; break;
            case 64:   bh1=(const float*)p; break;
            case 512:  Wh2=(const float*)p; break;
            case 8:    bh2=(const float*)p; break;
            default: break;
        }
    }
    float* out = (float*)d_out;
    int smem = 4*128*SLDH*2;
    cudaFuncSetAttribute(k_ffn, cudaFuncAttributeMaxDynamicSharedMemorySize, smem);

    k_init<<<1,32>>>();
    k_tables<<<260,256>>>(oe,Win);
    k_lt<<<33,256>>>(Wr,Win,bin);
    k_scalep<<<512,256>>>(W1,W2);
    k_sfin<<<1,32>>>();
    k_quant<<<8192,256>>>(W1,W2);
    k_route<<<BTOK/256,256>>>(op,a,b,c,out + (size_t)BTOK*8);
    k_part<<<1,256>>>();
    k_ffn<<<MAXBLK,256,smem>>>(op,a,b,c,Win,bin,Wh1,bh1,Wh2,bh2,out);
    k_aux<<<1,32>>>(out + (size_t)BTOK*9);
}